// round 1
// baseline (speedup 1.0000x reference)
#include <cuda_runtime.h>
#include <math.h>

#define T_  512
#define B_  256
#define D_  512
#define H_  512
#define H2_ (2*H_)
#define H3_ (3*H_)

// Scratch: precomputed input projections gi = ins @ Wi + bi   [T, B, 3H]
__device__ float g_gi[(size_t)T_ * B_ * H3_];
// Float reset mask: 1.0 keep, 0.0 reset                       [T, B]
__device__ float g_mask[T_ * B_];

// ---------------------------------------------------------------------------
// Reset-mask prep. `resets` dtype is ambiguous (bool8 vs int32/f32 words).
// Detect: in 4-byte encodings of {0,1}/{0.0f,1.0f}, a byte == 1 can only sit
// at offset % 4 == 0. bool8 random data has 1-bytes at odd offsets w.h.p.
// Only the first N bytes are touched for detection (safe under either size).
// ---------------------------------------------------------------------------
__global__ void prep_mask_kernel(const void* __restrict__ resets)
{
    const int N = T_ * B_;
    const unsigned char* b8 = (const unsigned char*)resets;
    int found = 0;
    for (int i = threadIdx.x; i < N; i += blockDim.x) {
        if ((i & 3) && b8[i] == 1) found = 1;
    }
    int is_byte = __syncthreads_or(found);
    if (is_byte) {
        for (int i = threadIdx.x; i < N; i += blockDim.x)
            g_mask[i] = b8[i] ? 0.0f : 1.0f;
    } else {
        const unsigned int* w32 = (const unsigned int*)resets;
        for (int i = threadIdx.x; i < N; i += blockDim.x)
            g_mask[i] = w32[i] ? 0.0f : 1.0f;
    }
}

// ---------------------------------------------------------------------------
// SGEMM + bias: C[M,N] = A[M,K] @ B[K,N] + bias[N]
// 128x128 tile, BK=8, 256 threads, 8x8 per-thread register tile.
// ---------------------------------------------------------------------------
__global__ __launch_bounds__(256)
void sgemm_bias_kernel(const float* __restrict__ A, const float* __restrict__ Bm,
                       const float* __restrict__ bias, float* __restrict__ C,
                       int M, int N, int K)
{
    __shared__ float As[8][128];
    __shared__ float Bs[8][128];

    const int tid = threadIdx.x;
    const int m0  = blockIdx.y * 128;
    const int n0  = blockIdx.x * 128;
    const int tr  = (tid >> 4) * 8;   // row offset of this thread's 8x8 tile
    const int tc  = (tid & 15) * 8;   // col offset

    const int arow = tid >> 1;
    const int ac4  = (tid & 1) * 4;
    const int brow = tid >> 5;
    const int bc4  = (tid & 31) * 4;

    const float* Aptr = A + (size_t)(m0 + arow) * K + ac4;
    const float* Bptr = Bm + (size_t)brow * N + n0 + bc4;

    float acc[8][8];
    #pragma unroll
    for (int i = 0; i < 8; i++)
        #pragma unroll
        for (int j = 0; j < 8; j++) acc[i][j] = 0.0f;

    for (int k0 = 0; k0 < K; k0 += 8) {
        float4 av = *(const float4*)(Aptr + k0);
        float4 bv = *(const float4*)(Bptr + (size_t)k0 * N);
        As[ac4 + 0][arow] = av.x;
        As[ac4 + 1][arow] = av.y;
        As[ac4 + 2][arow] = av.z;
        As[ac4 + 3][arow] = av.w;
        *(float4*)&Bs[brow][bc4] = bv;
        __syncthreads();

        #pragma unroll
        for (int k = 0; k < 8; k++) {
            float ra[8], rb[8];
            #pragma unroll
            for (int i = 0; i < 8; i++) ra[i] = As[k][tr + i];
            #pragma unroll
            for (int j = 0; j < 8; j++) rb[j] = Bs[k][tc + j];
            #pragma unroll
            for (int i = 0; i < 8; i++)
                #pragma unroll
                for (int j = 0; j < 8; j++)
                    acc[i][j] += ra[i] * rb[j];
        }
        __syncthreads();
    }

    float bv[8];
    #pragma unroll
    for (int j = 0; j < 8; j++) bv[j] = bias[n0 + tc + j];

    #pragma unroll
    for (int i = 0; i < 8; i++) {
        float* crow = C + (size_t)(m0 + tr + i) * N + n0 + tc;
        #pragma unroll
        for (int j = 0; j < 8; j++) crow[j] = acc[i][j] + bv[j];
    }
}

// ---------------------------------------------------------------------------
// One GRU step (launched T times, sequentially ordered by the stream).
// Block tile: 16 batch rows x 64 hidden cols, all 3 gates fused.
// Grid: (H/64 = 8, B/16 = 16) = 128 blocks, 256 threads.
//
//   h_in   = (t==0) ? rnn_state : ys[t-1], masked by g_mask[t]
//   C_r/z  = h_in @ Whrz (cols [0,H) / [H,2H))
//   C_n    = h_in @ Whn
//   r = sig(i_r + C_r); z = sig(i_z + C_z); n = tanh(i_n + r*(C_n + bhn))
//   ys[t]  = (1-z)*n + z*h_in
// ---------------------------------------------------------------------------
__global__ __launch_bounds__(256)
void gru_step_kernel(const float* __restrict__ rnn_state,
                     const float* __restrict__ Whrz,
                     const float* __restrict__ Whn,
                     const float* __restrict__ bhn,
                     float* __restrict__ ys,
                     int t)
{
    __shared__ float hs[16][33];      // 16 b-rows x 32 k, padded
    __shared__ float ws[32][192];     // 32 k x (3 gates * 64 h)
    __shared__ float sm[16];          // per-row reset mask

    const int tid = threadIdx.x;
    const int h0  = blockIdx.x * 64;
    const int b0  = blockIdx.y * 16;
    const int bb  = tid >> 4;         // 0..15
    const int hq  = tid & 15;         // 0..15 (quad of h)

    const float* hin = (t == 0) ? rnn_state : (ys + (size_t)(t - 1) * B_ * H_);

    if (tid < 16) sm[tid] = g_mask[t * B_ + b0 + tid];
    __syncthreads();

    float accr[4] = {0.f, 0.f, 0.f, 0.f};
    float accz[4] = {0.f, 0.f, 0.f, 0.f};
    float accn[4] = {0.f, 0.f, 0.f, 0.f};

    for (int k0 = 0; k0 < H_; k0 += 32) {
        // load masked h tile: 16x32
        #pragma unroll
        for (int i = tid; i < 16 * 32; i += 256) {
            int lb = i >> 5, lk = i & 31;
            hs[lb][lk] = hin[(size_t)(b0 + lb) * H_ + k0 + lk] * sm[lb];
        }
        // load W tile: 32 k-rows x 192 cols (r|z|n), float4 per thread x6
        #pragma unroll
        for (int j = tid; j < 32 * 48; j += 256) {
            int lk = j / 48;
            int q  = j % 48;
            int g  = q >> 4;          // 0=r 1=z 2=n
            int h4 = (q & 15) * 4;
            const float* src;
            if (g == 0)      src = Whrz + (size_t)(k0 + lk) * H2_ + h0 + h4;
            else if (g == 1) src = Whrz + (size_t)(k0 + lk) * H2_ + H_ + h0 + h4;
            else             src = Whn  + (size_t)(k0 + lk) * H_  + h0 + h4;
            *(float4*)&ws[lk][q * 4] = *(const float4*)src;
        }
        __syncthreads();

        #pragma unroll
        for (int kk = 0; kk < 32; kk++) {
            float hv = hs[bb][kk];
            float4 wr = *(const float4*)&ws[kk][       hq * 4];
            float4 wz = *(const float4*)&ws[kk][ 64  + hq * 4];
            float4 wn = *(const float4*)&ws[kk][ 128 + hq * 4];
            accr[0] += hv * wr.x; accr[1] += hv * wr.y; accr[2] += hv * wr.z; accr[3] += hv * wr.w;
            accz[0] += hv * wz.x; accz[1] += hv * wz.y; accz[2] += hv * wz.z; accz[3] += hv * wz.w;
            accn[0] += hv * wn.x; accn[1] += hv * wn.y; accn[2] += hv * wn.z; accn[3] += hv * wn.w;
        }
        __syncthreads();
    }

    // fused gate epilogue for 4 h-values
    const int b = b0 + bb;
    const int h = h0 + hq * 4;
    const float m = sm[bb];
    const float* gib  = g_gi + ((size_t)t * B_ + b) * H3_;
    const float* hrow = hin + (size_t)b * H_;
    float* yrow = ys + ((size_t)t * B_ + b) * H_;

    #pragma unroll
    for (int x = 0; x < 4; x++) {
        int hc = h + x;
        float ir = gib[hc];
        float iz = gib[H_  + hc];
        float in_ = gib[2 * H_ + hc];
        float hm = hrow[hc] * m;
        float r = 1.0f / (1.0f + expf(-(ir + accr[x])));
        float z = 1.0f / (1.0f + expf(-(iz + accz[x])));
        float n = tanhf(in_ + r * (accn[x] + bhn[hc]));
        yrow[hc] = (1.0f - z) * n + z * hm;
    }
}

// ---------------------------------------------------------------------------
// Launch: prep mask -> gi GEMM -> 512 sequential GRU steps -> final_h copy.
// Output layout: d_out[0 : B*H] = final_h, d_out[B*H : ] = ys[T,B,H].
// ---------------------------------------------------------------------------
extern "C" void kernel_launch(void* const* d_in, const int* in_sizes, int n_in,
                              void* d_out, int out_size)
{
    const float* rnn_state = (const float*)d_in[0];   // [B, H]
    const float* ins       = (const float*)d_in[1];   // [T, B, D]
    const void*  resets    = d_in[2];                 // [T, B] (dtype detected)
    const float* Wi        = (const float*)d_in[3];   // [D, 3H]
    const float* bi        = (const float*)d_in[4];   // [3H]
    const float* Whrz      = (const float*)d_in[5];   // [H, 2H]
    const float* Whn       = (const float*)d_in[6];   // [H, H]
    const float* bhn       = (const float*)d_in[7];   // [H]

    float* final_h = (float*)d_out;
    float* ys      = (float*)d_out + (size_t)B_ * H_;

    float* gi_ptr = nullptr;
    cudaGetSymbolAddress((void**)&gi_ptr, g_gi);

    // 1) reset mask
    prep_mask_kernel<<<1, 256>>>(resets);

    // 2) gi = ins @ Wi + bi   (M=T*B, N=3H, K=D)
    {
        dim3 grid(H3_ / 128, (T_ * B_) / 128);
        sgemm_bias_kernel<<<grid, 256>>>(ins, Wi, bi, gi_ptr, T_ * B_, H3_, D_);
    }

    // 3) sequential scan
    {
        dim3 grid(H_ / 64, B_ / 16);
        for (int t = 0; t < T_; t++)
            gru_step_kernel<<<grid, 256>>>(rnn_state, Whrz, Whn, bhn, ys, t);
    }

    // 4) final_h = ys[T-1]
    cudaMemcpyAsync(final_h, ys + (size_t)(T_ - 1) * B_ * H_,
                    (size_t)B_ * H_ * sizeof(float),
                    cudaMemcpyDeviceToDevice, 0);
}

// round 2
// speedup vs baseline: 2.4005x; 2.4005x over previous
#include <cuda_runtime.h>
#include <math.h>

#define T_  512
#define B_  256
#define D_  512
#define H_  512
#define H2_ (2*H_)
#define H3_ (3*H_)

#define NBLK 128
#define NTHR 256

typedef unsigned long long ull;

// Scratch: precomputed input projections gi = ins @ Wi + bi   [T, B, 3H]
__device__ float g_gi[(size_t)T_ * B_ * H3_];
// Float reset mask: 1.0 keep, 0.0 reset                       [T, B]
__device__ float g_mask[T_ * B_];
// Software grid barrier state
__device__ unsigned g_cnt = 0;
__device__ volatile unsigned g_gen = 0;

// ---------------------------------------------------------------------------
// f32x2 packed-FMA helpers (ptxas will not emit FFMA2 from plain C++)
// ---------------------------------------------------------------------------
__device__ __forceinline__ ull pack2(float x) {
    ull r; unsigned u = __float_as_uint(x);
    asm("mov.b64 %0, {%1, %1};" : "=l"(r) : "r"(u));
    return r;
}
__device__ __forceinline__ void fma2(ull& d, ull a, ull b) {
    asm("fma.rn.f32x2 %0, %1, %2, %0;" : "+l"(d) : "l"(a), "l"(b));
}
__device__ __forceinline__ float2 unpk(ull v) {
    float2 f;
    asm("mov.b64 {%0, %1}, %2;" : "=f"(f.x), "=f"(f.y) : "l"(v));
    return f;
}

// ---------------------------------------------------------------------------
// Reset-mask prep (resets dtype: bool8 vs 4-byte words, detected on device).
// ---------------------------------------------------------------------------
__global__ void prep_mask_kernel(const void* __restrict__ resets)
{
    const int N = T_ * B_;
    const unsigned char* b8 = (const unsigned char*)resets;
    int found = 0;
    for (int i = threadIdx.x; i < N; i += blockDim.x) {
        if ((i & 3) && b8[i] == 1) found = 1;
    }
    int is_byte = __syncthreads_or(found);
    if (is_byte) {
        for (int i = threadIdx.x; i < N; i += blockDim.x)
            g_mask[i] = b8[i] ? 0.0f : 1.0f;
    } else {
        const unsigned int* w32 = (const unsigned int*)resets;
        for (int i = threadIdx.x; i < N; i += blockDim.x)
            g_mask[i] = w32[i] ? 0.0f : 1.0f;
    }
}

// ---------------------------------------------------------------------------
// SGEMM + bias: C[M,N] = A[M,K] @ B[K,N] + bias[N]   (f32x2 FMA version)
// 128x128 tile, BK=8, 256 threads. Per-thread: rows tr..tr+7,
// cols {32*j + 2*q, +1} j=0..3 (conflict-free LDS.64 on B fragments).
// ---------------------------------------------------------------------------
__global__ __launch_bounds__(256, 2)
void sgemm_bias_kernel(const float* __restrict__ A, const float* __restrict__ Bm,
                       const float* __restrict__ bias, float* __restrict__ C,
                       int M, int N, int K)
{
    __shared__ float As[8][128];
    __shared__ float Bs[8][128];

    const int tid = threadIdx.x;
    const int m0  = blockIdx.y * 128;
    const int n0  = blockIdx.x * 128;
    const int tr  = (tid >> 4) * 8;   // row offset of this thread's 8-row strip
    const int q   = tid & 15;         // col group

    const int arow = tid >> 1;
    const int ac4  = (tid & 1) * 4;
    const int brow = tid >> 5;
    const int bc4  = (tid & 31) * 4;

    const float* Aptr = A + (size_t)(m0 + arow) * K + ac4;
    const float* Bptr = Bm + (size_t)brow * N + n0 + bc4;

    ull acc[8][4];
    #pragma unroll
    for (int i = 0; i < 8; i++)
        #pragma unroll
        for (int j = 0; j < 4; j++) acc[i][j] = 0ull;

    for (int k0 = 0; k0 < K; k0 += 8) {
        float4 av = *(const float4*)(Aptr + k0);
        float4 bv = *(const float4*)(Bptr + (size_t)k0 * N);
        As[ac4 + 0][arow] = av.x;
        As[ac4 + 1][arow] = av.y;
        As[ac4 + 2][arow] = av.z;
        As[ac4 + 3][arow] = av.w;
        *(float4*)&Bs[brow][bc4] = bv;
        __syncthreads();

        #pragma unroll
        for (int k = 0; k < 8; k++) {
            float4 a0 = *(const float4*)&As[k][tr];
            float4 a1 = *(const float4*)&As[k][tr + 4];
            ull ap[8];
            ap[0] = pack2(a0.x); ap[1] = pack2(a0.y);
            ap[2] = pack2(a0.z); ap[3] = pack2(a0.w);
            ap[4] = pack2(a1.x); ap[5] = pack2(a1.y);
            ap[6] = pack2(a1.z); ap[7] = pack2(a1.w);
            ull rb[4];
            #pragma unroll
            for (int j = 0; j < 4; j++)
                rb[j] = *(const ull*)&Bs[k][32 * j + 2 * q];
            #pragma unroll
            for (int i = 0; i < 8; i++)
                #pragma unroll
                for (int j = 0; j < 4; j++)
                    fma2(acc[i][j], ap[i], rb[j]);
        }
        __syncthreads();
    }

    float2 bv2[4];
    #pragma unroll
    for (int j = 0; j < 4; j++)
        bv2[j] = *(const float2*)&bias[n0 + 32 * j + 2 * q];

    #pragma unroll
    for (int i = 0; i < 8; i++) {
        float* crow = C + (size_t)(m0 + tr + i) * N + n0;
        #pragma unroll
        for (int j = 0; j < 4; j++) {
            float2 v = unpk(acc[i][j]);
            v.x += bv2[j].x;
            v.y += bv2[j].y;
            *(float2*)&crow[32 * j + 2 * q] = v;
        }
    }
}

// ---------------------------------------------------------------------------
// Grid-wide software barrier (all NBLK blocks co-resident).
// Release/acquire via threadfence around the L2 atomics; bar.sync chains
// per-thread stores into tid0's gpu-scope release (PTX mem model transitivity).
// ---------------------------------------------------------------------------
__device__ __forceinline__ void grid_sync()
{
    __syncthreads();
    if (threadIdx.x == 0) {
        unsigned g = g_gen;
        __threadfence();
        if (atomicAdd(&g_cnt, 1) == NBLK - 1) {
            g_cnt = 0;
            __threadfence();
            g_gen = g + 1;
        } else {
            while (g_gen == g) { __nanosleep(32); }
        }
        __threadfence();
    }
    __syncthreads();
}

// ---------------------------------------------------------------------------
// Persistent GRU scan. 128 blocks = (8 b-tiles of 32) x (16 h-tiles of 32).
// W slice (3 gates x 32 h x 512 k = 192KB) lives in SMEM for ALL 512 steps.
// Per thread: 2 batch rows x 2 h cols (f32x2), 6 packed accumulators.
// h-state is cross-SM data -> __ldcv (L2) loads; grid barrier between steps.
// ---------------------------------------------------------------------------
#define WS_F2   (512 * 48)                   // float2 elems of W slice
#define HS_STR  68                           // padded hs row stride (floats)
#define SMEM_BYTES (WS_F2 * 8 + 32 * HS_STR * 4 + 128)

__global__ __launch_bounds__(NTHR, 1)
void gru_scan_kernel(const float* __restrict__ rnn_state,
                     const float* __restrict__ Whrz,
                     const float* __restrict__ Whn,
                     const float* __restrict__ bhn,
                     const float* __restrict__ gi,
                     float* __restrict__ ys)
{
    extern __shared__ char smraw[];
    float2* ws2 = (float2*)smraw;                              // [512][48]
    float*  hs  = (float*)(smraw + WS_F2 * 8);                 // [32][68]
    float*  sm  = (float*)(smraw + WS_F2 * 8 + 32 * HS_STR * 4);

    const int tid = threadIdx.x;
    const int bid = blockIdx.x;
    const int hti = bid & 15, bti = bid >> 4;
    const int hb  = hti * 32;          // h-col base
    const int b0  = bti * 32;          // batch base
    const int th  = tid & 15;          // h pair index (2h per thread)
    const int tb  = tid >> 4;          // 0..15
    const int bb0 = tb * 2, bb1 = bb0 + 1;

    // ---- load resident W slice: ws2[k][g*16 + j] = gate g cols (hb+2j, +1) at row k
    for (int i = tid; i < WS_F2; i += NTHR) {
        int k = i / 48, c = i % 48, g = c >> 4, j = (c & 15) * 2;
        const float* src;
        if (g == 0)      src = Whrz + (size_t)k * H2_ + hb + j;
        else if (g == 1) src = Whrz + (size_t)k * H2_ + H_ + hb + j;
        else             src = Whn  + (size_t)k * H_  + hb + j;
        ws2[i] = *(const float2*)src;
    }

    // hs cooperative-load slots: 512 float4 per chunk, 2 per thread
    const int s0  = tid,        s1  = tid + NTHR;
    const int lb0 = s0 >> 4,    kq0 = (s0 & 15) * 4;
    const int lb1 = s1 >> 4,    kq1 = (s1 & 15) * 4;

    for (int t = 0; t < T_; t++) {
        const float* hin = (t == 0) ? rnn_state : (ys + (size_t)(t - 1) * B_ * H_);
        if (tid < 32) sm[tid] = g_mask[t * B_ + b0 + tid];

        const float* hrow0 = hin + (size_t)(b0 + lb0) * H_;
        const float* hrow1 = hin + (size_t)(b0 + lb1) * H_;

        float4 p0 = __ldcv((const float4*)(hrow0 + kq0));
        float4 p1 = __ldcv((const float4*)(hrow1 + kq1));

        ull ar0 = 0, ar1 = 0, az0 = 0, az1 = 0, an0 = 0, an1 = 0;

        for (int c = 0; c < 8; c++) {
            __syncthreads();                       // hs free + sm ready
            float m0 = sm[lb0], m1 = sm[lb1];
            float4 q0 = make_float4(p0.x * m0, p0.y * m0, p0.z * m0, p0.w * m0);
            float4 q1 = make_float4(p1.x * m1, p1.y * m1, p1.z * m1, p1.w * m1);
            *(float4*)&hs[lb0 * HS_STR + kq0] = q0;
            *(float4*)&hs[lb1 * HS_STR + kq1] = q1;
            if (c < 7) {                           // prefetch next chunk
                p0 = __ldcv((const float4*)(hrow0 + (c + 1) * 64 + kq0));
                p1 = __ldcv((const float4*)(hrow1 + (c + 1) * 64 + kq1));
            }
            __syncthreads();                       // hs ready

            const float2* wk = ws2 + (size_t)c * 64 * 48 + th;
            #pragma unroll 8
            for (int kk = 0; kk < 64; kk++) {
                float hv0 = hs[bb0 * HS_STR + kk];
                float hv1 = hs[bb1 * HS_STR + kk];
                ull h0p = pack2(hv0);
                ull h1p = pack2(hv1);
                const float2* w = wk + kk * 48;
                ull wr = *(const ull*)(w);
                ull wz = *(const ull*)(w + 16);
                ull wn = *(const ull*)(w + 32);
                fma2(ar0, h0p, wr); fma2(az0, h0p, wz); fma2(an0, h0p, wn);
                fma2(ar1, h1p, wr); fma2(az1, h1p, wz); fma2(an1, h1p, wn);
            }
        }

        // ---- fused gate epilogue: 2 b-rows x 2 h-cols
        const int hc = hb + th * 2;
        const float2 bh2 = *(const float2*)(bhn + hc);

        #pragma unroll
        for (int r = 0; r < 2; r++) {
            const int bb = (r == 0) ? bb0 : bb1;
            const int b  = b0 + bb;
            const float m = sm[bb];
            float2 cr = unpk(r == 0 ? ar0 : ar1);
            float2 cz = unpk(r == 0 ? az0 : az1);
            float2 cn = unpk(r == 0 ? an0 : an1);

            const float* gib = gi + ((size_t)t * B_ + b) * H3_;
            float2 ir = *(const float2*)(gib + hc);
            float2 iz = *(const float2*)(gib + H_ + hc);
            float2 in_ = *(const float2*)(gib + 2 * H_ + hc);
            float2 ho = __ldcv((const float2*)(hin + (size_t)b * H_ + hc));
            float hm0 = ho.x * m, hm1 = ho.y * m;

            float rg0 = 1.0f / (1.0f + expf(-(ir.x + cr.x)));
            float rg1 = 1.0f / (1.0f + expf(-(ir.y + cr.y)));
            float zg0 = 1.0f / (1.0f + expf(-(iz.x + cz.x)));
            float zg1 = 1.0f / (1.0f + expf(-(iz.y + cz.y)));
            float ng0 = tanhf(in_.x + rg0 * (cn.x + bh2.x));
            float ng1 = tanhf(in_.y + rg1 * (cn.y + bh2.y));

            float2 out;
            out.x = (1.0f - zg0) * ng0 + zg0 * hm0;
            out.y = (1.0f - zg1) * ng1 + zg1 * hm1;
            *(float2*)(ys + ((size_t)t * B_ + b) * H_ + hc) = out;
        }

        grid_sync();
    }
}

// ---------------------------------------------------------------------------
// Launch: prep mask -> gi GEMM -> persistent scan -> final_h copy.
// Output layout: d_out[0 : B*H] = final_h, d_out[B*H : ] = ys[T,B,H].
// ---------------------------------------------------------------------------
extern "C" void kernel_launch(void* const* d_in, const int* in_sizes, int n_in,
                              void* d_out, int out_size)
{
    const float* rnn_state = (const float*)d_in[0];   // [B, H]
    const float* ins       = (const float*)d_in[1];   // [T, B, D]
    const void*  resets    = d_in[2];                 // [T, B]
    const float* Wi        = (const float*)d_in[3];   // [D, 3H]
    const float* bi        = (const float*)d_in[4];   // [3H]
    const float* Whrz      = (const float*)d_in[5];   // [H, 2H]
    const float* Whn       = (const float*)d_in[6];   // [H, H]
    const float* bhn       = (const float*)d_in[7];   // [H]

    float* final_h = (float*)d_out;
    float* ys      = (float*)d_out + (size_t)B_ * H_;

    float* gi_ptr = nullptr;
    cudaGetSymbolAddress((void**)&gi_ptr, g_gi);

    // persistent kernel needs the big SMEM carveout (idempotent; every call)
    cudaFuncSetAttribute(gru_scan_kernel,
                         cudaFuncAttributeMaxDynamicSharedMemorySize, SMEM_BYTES);

    // 1) reset mask
    prep_mask_kernel<<<1, 1024>>>(resets);

    // 2) gi = ins @ Wi + bi   (M=T*B, N=3H, K=D)
    {
        dim3 grid(H3_ / 128, (T_ * B_) / 128);
        sgemm_bias_kernel<<<grid, 256>>>(ins, Wi, bi, gi_ptr, T_ * B_, H3_, D_);
    }

    // 3) persistent sequential scan (all 512 steps in one kernel)
    gru_scan_kernel<<<NBLK, NTHR, SMEM_BYTES>>>(rnn_state, Whrz, Whn, bhn,
                                                gi_ptr, ys);

    // 4) final_h = ys[T-1]
    cudaMemcpyAsync(final_h, ys + (size_t)(T_ - 1) * B_ * H_,
                    (size_t)B_ * H_ * sizeof(float),
                    cudaMemcpyDeviceToDevice, 0);
}

// round 3
// speedup vs baseline: 2.4037x; 1.0013x over previous
#include <cuda_runtime.h>
#include <math.h>

#define T_  512
#define B_  256
#define D_  512
#define H_  512
#define H2_ (2*H_)
#define H3_ (3*H_)

#define NBLK 128
#define NTHR 256

typedef unsigned long long ull;

// Scratch: precomputed input projections gi = ins @ Wi + bi   [T, B, 3H]
__device__ float g_gi[(size_t)T_ * B_ * H3_];
// Float reset mask: 1.0 keep, 0.0 reset                       [T, B]
__device__ float g_mask[T_ * B_];
// Software grid barrier state
__device__ unsigned g_cnt = 0;
__device__ volatile unsigned g_gen = 0;

// ---------------------------------------------------------------------------
// f32x2 packed-FMA helpers (ptxas will not emit FFMA2 from plain C++)
// ---------------------------------------------------------------------------
__device__ __forceinline__ ull pack2(float x) {
    ull r; unsigned u = __float_as_uint(x);
    asm("mov.b64 %0, {%1, %1};" : "=l"(r) : "r"(u));
    return r;
}
__device__ __forceinline__ void fma2(ull& d, ull a, ull b) {
    asm("fma.rn.f32x2 %0, %1, %2, %0;" : "+l"(d) : "l"(a), "l"(b));
}
__device__ __forceinline__ float2 unpk(ull v) {
    float2 f;
    asm("mov.b64 {%0, %1}, %2;" : "=f"(f.x), "=f"(f.y) : "l"(v));
    return f;
}

// ---------------------------------------------------------------------------
// Reset-mask prep (resets dtype: bool8 vs 4-byte words, detected on device).
// ---------------------------------------------------------------------------
__global__ void prep_mask_kernel(const void* __restrict__ resets)
{
    const int N = T_ * B_;
    const unsigned char* b8 = (const unsigned char*)resets;
    int found = 0;
    for (int i = threadIdx.x; i < N; i += blockDim.x) {
        if ((i & 3) && b8[i] == 1) found = 1;
    }
    int is_byte = __syncthreads_or(found);
    if (is_byte) {
        for (int i = threadIdx.x; i < N; i += blockDim.x)
            g_mask[i] = b8[i] ? 0.0f : 1.0f;
    } else {
        const unsigned int* w32 = (const unsigned int*)resets;
        for (int i = threadIdx.x; i < N; i += blockDim.x)
            g_mask[i] = w32[i] ? 0.0f : 1.0f;
    }
}

// ---------------------------------------------------------------------------
// SGEMM + bias: C[M,N] = A[M,K] @ B[K,N] + bias[N]   (f32x2 FMA version)
// 128x128 tile, BK=8, 256 threads. Per-thread: rows tr..tr+7,
// cols {32*j + 2*q, +1} j=0..3 (conflict-free LDS.64 on B fragments).
// ---------------------------------------------------------------------------
__global__ __launch_bounds__(256, 2)
void sgemm_bias_kernel(const float* __restrict__ A, const float* __restrict__ Bm,
                       const float* __restrict__ bias, float* __restrict__ C,
                       int M, int N, int K)
{
    __shared__ float As[8][128];
    __shared__ float Bs[8][128];

    const int tid = threadIdx.x;
    const int m0  = blockIdx.y * 128;
    const int n0  = blockIdx.x * 128;
    const int tr  = (tid >> 4) * 8;   // row offset of this thread's 8-row strip
    const int q   = tid & 15;         // col group

    const int arow = tid >> 1;
    const int ac4  = (tid & 1) * 4;
    const int brow = tid >> 5;
    const int bc4  = (tid & 31) * 4;

    const float* Aptr = A + (size_t)(m0 + arow) * K + ac4;
    const float* Bptr = Bm + (size_t)brow * N + n0 + bc4;

    ull acc[8][4];
    #pragma unroll
    for (int i = 0; i < 8; i++)
        #pragma unroll
        for (int j = 0; j < 4; j++) acc[i][j] = 0ull;

    for (int k0 = 0; k0 < K; k0 += 8) {
        float4 av = *(const float4*)(Aptr + k0);
        float4 bv = *(const float4*)(Bptr + (size_t)k0 * N);
        As[ac4 + 0][arow] = av.x;
        As[ac4 + 1][arow] = av.y;
        As[ac4 + 2][arow] = av.z;
        As[ac4 + 3][arow] = av.w;
        *(float4*)&Bs[brow][bc4] = bv;
        __syncthreads();

        #pragma unroll
        for (int k = 0; k < 8; k++) {
            float4 a0 = *(const float4*)&As[k][tr];
            float4 a1 = *(const float4*)&As[k][tr + 4];
            ull ap[8];
            ap[0] = pack2(a0.x); ap[1] = pack2(a0.y);
            ap[2] = pack2(a0.z); ap[3] = pack2(a0.w);
            ap[4] = pack2(a1.x); ap[5] = pack2(a1.y);
            ap[6] = pack2(a1.z); ap[7] = pack2(a1.w);
            ull rb[4];
            #pragma unroll
            for (int j = 0; j < 4; j++)
                rb[j] = *(const ull*)&Bs[k][32 * j + 2 * q];
            #pragma unroll
            for (int i = 0; i < 8; i++)
                #pragma unroll
                for (int j = 0; j < 4; j++)
                    fma2(acc[i][j], ap[i], rb[j]);
        }
        __syncthreads();
    }

    float2 bv2[4];
    #pragma unroll
    for (int j = 0; j < 4; j++)
        bv2[j] = *(const float2*)&bias[n0 + 32 * j + 2 * q];

    #pragma unroll
    for (int i = 0; i < 8; i++) {
        float* crow = C + (size_t)(m0 + tr + i) * N + n0;
        #pragma unroll
        for (int j = 0; j < 4; j++) {
            float2 v = unpk(acc[i][j]);
            v.x += bv2[j].x;
            v.y += bv2[j].y;
            *(float2*)&crow[32 * j + 2 * q] = v;
        }
    }
}

// ---------------------------------------------------------------------------
// Grid-wide software barrier (all NBLK blocks co-resident).
// Release/acquire via threadfence around the L2 atomics; bar.sync chains
// per-thread stores into tid0's gpu-scope release (PTX mem model transitivity).
// ---------------------------------------------------------------------------
__device__ __forceinline__ void grid_sync()
{
    __syncthreads();
    if (threadIdx.x == 0) {
        unsigned g = g_gen;
        __threadfence();
        if (atomicAdd(&g_cnt, 1) == NBLK - 1) {
            g_cnt = 0;
            __threadfence();
            g_gen = g + 1;
        } else {
            while (g_gen == g) { __nanosleep(32); }
        }
        __threadfence();
    }
    __syncthreads();
}

// ---------------------------------------------------------------------------
// Persistent GRU scan. 128 blocks = (8 b-tiles of 32) x (16 h-tiles of 32).
// W slice (3 gates x 32 h x 512 k = 192KB) lives in SMEM for ALL 512 steps.
// Per thread: 2 batch rows x 2 h cols (f32x2), 6 packed accumulators.
// h-state is cross-SM data -> __ldcv (L2) loads; grid barrier between steps.
// ---------------------------------------------------------------------------
#define WS_F2   (512 * 48)                   // float2 elems of W slice
#define HS_STR  68                           // padded hs row stride (floats)
#define SMEM_BYTES (WS_F2 * 8 + 32 * HS_STR * 4 + 128)

__global__ __launch_bounds__(NTHR, 1)
void gru_scan_kernel(const float* __restrict__ rnn_state,
                     const float* __restrict__ Whrz,
                     const float* __restrict__ Whn,
                     const float* __restrict__ bhn,
                     const float* __restrict__ gi,
                     float* __restrict__ ys)
{
    extern __shared__ char smraw[];
    float2* ws2 = (float2*)smraw;                              // [512][48]
    float*  hs  = (float*)(smraw + WS_F2 * 8);                 // [32][68]
    float*  sm  = (float*)(smraw + WS_F2 * 8 + 32 * HS_STR * 4);

    const int tid = threadIdx.x;
    const int bid = blockIdx.x;
    const int hti = bid & 15, bti = bid >> 4;
    const int hb  = hti * 32;          // h-col base
    const int b0  = bti * 32;          // batch base
    const int th  = tid & 15;          // h pair index (2h per thread)
    const int tb  = tid >> 4;          // 0..15
    const int bb0 = tb * 2, bb1 = bb0 + 1;

    // ---- load resident W slice: ws2[k][g*16 + j] = gate g cols (hb+2j, +1) at row k
    for (int i = tid; i < WS_F2; i += NTHR) {
        int k = i / 48, c = i % 48, g = c >> 4, j = (c & 15) * 2;
        const float* src;
        if (g == 0)      src = Whrz + (size_t)k * H2_ + hb + j;
        else if (g == 1) src = Whrz + (size_t)k * H2_ + H_ + hb + j;
        else             src = Whn  + (size_t)k * H_  + hb + j;
        ws2[i] = *(const float2*)src;
    }

    // hs cooperative-load slots: 512 float4 per chunk, 2 per thread
    const int s0  = tid,        s1  = tid + NTHR;
    const int lb0 = s0 >> 4,    kq0 = (s0 & 15) * 4;
    const int lb1 = s1 >> 4,    kq1 = (s1 & 15) * 4;

    for (int t = 0; t < T_; t++) {
        const float* hin = (t == 0) ? rnn_state : (ys + (size_t)(t - 1) * B_ * H_);
        if (tid < 32) sm[tid] = g_mask[t * B_ + b0 + tid];

        const float* hrow0 = hin + (size_t)(b0 + lb0) * H_;
        const float* hrow1 = hin + (size_t)(b0 + lb1) * H_;

        float4 p0 = __ldcv((const float4*)(hrow0 + kq0));
        float4 p1 = __ldcv((const float4*)(hrow1 + kq1));

        ull ar0 = 0, ar1 = 0, az0 = 0, az1 = 0, an0 = 0, an1 = 0;

        for (int c = 0; c < 8; c++) {
            __syncthreads();                       // hs free + sm ready
            float m0 = sm[lb0], m1 = sm[lb1];
            float4 q0 = make_float4(p0.x * m0, p0.y * m0, p0.z * m0, p0.w * m0);
            float4 q1 = make_float4(p1.x * m1, p1.y * m1, p1.z * m1, p1.w * m1);
            *(float4*)&hs[lb0 * HS_STR + kq0] = q0;
            *(float4*)&hs[lb1 * HS_STR + kq1] = q1;
            if (c < 7) {                           // prefetch next chunk
                p0 = __ldcv((const float4*)(hrow0 + (c + 1) * 64 + kq0));
                p1 = __ldcv((const float4*)(hrow1 + (c + 1) * 64 + kq1));
            }
            __syncthreads();                       // hs ready

            const float2* wk = ws2 + (size_t)c * 64 * 48 + th;
            #pragma unroll 8
            for (int kk = 0; kk < 64; kk++) {
                float hv0 = hs[bb0 * HS_STR + kk];
                float hv1 = hs[bb1 * HS_STR + kk];
                ull h0p = pack2(hv0);
                ull h1p = pack2(hv1);
                const float2* w = wk + kk * 48;
                ull wr = *(const ull*)(w);
                ull wz = *(const ull*)(w + 16);
                ull wn = *(const ull*)(w + 32);
                fma2(ar0, h0p, wr); fma2(az0, h0p, wz); fma2(an0, h0p, wn);
                fma2(ar1, h1p, wr); fma2(az1, h1p, wz); fma2(an1, h1p, wn);
            }
        }

        // ---- fused gate epilogue: 2 b-rows x 2 h-cols
        const int hc = hb + th * 2;
        const float2 bh2 = *(const float2*)(bhn + hc);

        #pragma unroll
        for (int r = 0; r < 2; r++) {
            const int bb = (r == 0) ? bb0 : bb1;
            const int b  = b0 + bb;
            const float m = sm[bb];
            float2 cr = unpk(r == 0 ? ar0 : ar1);
            float2 cz = unpk(r == 0 ? az0 : az1);
            float2 cn = unpk(r == 0 ? an0 : an1);

            const float* gib = gi + ((size_t)t * B_ + b) * H3_;
            float2 ir = *(const float2*)(gib + hc);
            float2 iz = *(const float2*)(gib + H_ + hc);
            float2 in_ = *(const float2*)(gib + 2 * H_ + hc);
            float2 ho = __ldcv((const float2*)(hin + (size_t)b * H_ + hc));
            float hm0 = ho.x * m, hm1 = ho.y * m;

            float rg0 = 1.0f / (1.0f + expf(-(ir.x + cr.x)));
            float rg1 = 1.0f / (1.0f + expf(-(ir.y + cr.y)));
            float zg0 = 1.0f / (1.0f + expf(-(iz.x + cz.x)));
            float zg1 = 1.0f / (1.0f + expf(-(iz.y + cz.y)));
            float ng0 = tanhf(in_.x + rg0 * (cn.x + bh2.x));
            float ng1 = tanhf(in_.y + rg1 * (cn.y + bh2.y));

            float2 out;
            out.x = (1.0f - zg0) * ng0 + zg0 * hm0;
            out.y = (1.0f - zg1) * ng1 + zg1 * hm1;
            *(float2*)(ys + ((size_t)t * B_ + b) * H_ + hc) = out;
        }

        grid_sync();
    }
}

// ---------------------------------------------------------------------------
// Launch: prep mask -> gi GEMM -> persistent scan -> final_h copy.
// Output layout: d_out[0 : B*H] = final_h, d_out[B*H : ] = ys[T,B,H].
// ---------------------------------------------------------------------------
extern "C" void kernel_launch(void* const* d_in, const int* in_sizes, int n_in,
                              void* d_out, int out_size)
{
    const float* rnn_state = (const float*)d_in[0];   // [B, H]
    const float* ins       = (const float*)d_in[1];   // [T, B, D]
    const void*  resets    = d_in[2];                 // [T, B]
    const float* Wi        = (const float*)d_in[3];   // [D, 3H]
    const float* bi        = (const float*)d_in[4];   // [3H]
    const float* Whrz      = (const float*)d_in[5];   // [H, 2H]
    const float* Whn       = (const float*)d_in[6];   // [H, H]
    const float* bhn       = (const float*)d_in[7];   // [H]

    float* final_h = (float*)d_out;
    float* ys      = (float*)d_out + (size_t)B_ * H_;

    float* gi_ptr = nullptr;
    cudaGetSymbolAddress((void**)&gi_ptr, g_gi);

    // persistent kernel needs the big SMEM carveout (idempotent; every call)
    cudaFuncSetAttribute(gru_scan_kernel,
                         cudaFuncAttributeMaxDynamicSharedMemorySize, SMEM_BYTES);

    // 1) reset mask
    prep_mask_kernel<<<1, 1024>>>(resets);

    // 2) gi = ins @ Wi + bi   (M=T*B, N=3H, K=D)
    {
        dim3 grid(H3_ / 128, (T_ * B_) / 128);
        sgemm_bias_kernel<<<grid, 256>>>(ins, Wi, bi, gi_ptr, T_ * B_, H3_, D_);
    }

    // 3) persistent sequential scan (all 512 steps in one kernel)
    gru_scan_kernel<<<NBLK, NTHR, SMEM_BYTES>>>(rnn_state, Whrz, Whn, bhn,
                                                gi_ptr, ys);

    // 4) final_h = ys[T-1]
    cudaMemcpyAsync(final_h, ys + (size_t)(T_ - 1) * B_ * H_,
                    (size_t)B_ * H_ * sizeof(float),
                    cudaMemcpyDeviceToDevice, 0);
}

// round 5
// speedup vs baseline: 2.6849x; 1.1170x over previous
#include <cuda_runtime.h>
#include <cuda_bf16.h>
#include <math.h>
#include <cstdint>

#define T_  512
#define B_  256
#define D_  512
#define H_  512
#define H2_ (2*H_)
#define H3_ (3*H_)

#define NBLK 128
#define NTHR 256

typedef unsigned long long ull;

// ===========================================================================
// Global scratch
// ===========================================================================
__device__ float g_gi[(size_t)T_ * B_ * H3_];       // gi = ins @ Wi + bi
__device__ float g_mask[T_ * B_];
__device__ unsigned g_cnt8[8 * 32];                 // per-group barrier state
__device__ volatile unsigned g_gen8[8 * 32];

// ===========================================================================
// f32x2 packed-FMA helpers
// ===========================================================================
__device__ __forceinline__ ull pack2(float x) {
    ull r; unsigned u = __float_as_uint(x);
    asm("mov.b64 %0, {%1, %1};" : "=l"(r) : "r"(u));
    return r;
}
__device__ __forceinline__ void fma2(ull& d, ull a, ull b) {
    asm("fma.rn.f32x2 %0, %1, %2, %0;" : "+l"(d) : "l"(a), "l"(b));
}
__device__ __forceinline__ float2 unpk(ull v) {
    float2 f;
    asm("mov.b64 {%0, %1}, %2;" : "=f"(f.x), "=f"(f.y) : "l"(v));
    return f;
}

// ===========================================================================
// Reset-mask prep (bool8 vs 4-byte dtype detection)
// ===========================================================================
__global__ void prep_mask_kernel(const void* __restrict__ resets)
{
    const int N = T_ * B_;
    const unsigned char* b8 = (const unsigned char*)resets;
    int found = 0;
    for (int i = threadIdx.x; i < N; i += blockDim.x)
        if ((i & 3) && b8[i] == 1) found = 1;
    int is_byte = __syncthreads_or(found);
    if (is_byte) {
        for (int i = threadIdx.x; i < N; i += blockDim.x)
            g_mask[i] = b8[i] ? 0.0f : 1.0f;
    } else {
        const unsigned int* w32 = (const unsigned int*)resets;
        for (int i = threadIdx.x; i < N; i += blockDim.x)
            g_mask[i] = w32[i] ? 0.0f : 1.0f;
    }
}

// ===========================================================================
// gi GEMM: C[M,3H] = ins[M,D] @ Wi[D,3H] + bi, via mma.sync bf16 split
//   D += Ahi*Bhi + Alo*Bhi + Ahi*Blo   (fp32 accumulate)
// Block tile 128m x 128n x 32k; 8 warps, warp tile 64m x 32n.
// ===========================================================================
#define SAK 40          // padded k-stride (bf16 elems) for SMEM tiles

__device__ __forceinline__ void mma_bf16(float* c, const unsigned* a,
                                         const unsigned* b) {
    asm volatile(
        "mma.sync.aligned.m16n8k16.row.col.f32.bf16.bf16.f32 "
        "{%0,%1,%2,%3}, {%4,%5,%6,%7}, {%8,%9}, {%0,%1,%2,%3};"
        : "+f"(c[0]), "+f"(c[1]), "+f"(c[2]), "+f"(c[3])
        : "r"(a[0]), "r"(a[1]), "r"(a[2]), "r"(a[3]), "r"(b[0]), "r"(b[1]));
}

__device__ __forceinline__ void split_f4(float4 v, ull& hi, ull& lo) {
    __nv_bfloat16 h0 = __float2bfloat16(v.x);
    __nv_bfloat16 h1 = __float2bfloat16(v.y);
    __nv_bfloat16 h2 = __float2bfloat16(v.z);
    __nv_bfloat16 h3 = __float2bfloat16(v.w);
    __nv_bfloat16 l0 = __float2bfloat16(v.x - __bfloat162float(h0));
    __nv_bfloat16 l1 = __float2bfloat16(v.y - __bfloat162float(h1));
    __nv_bfloat16 l2 = __float2bfloat16(v.z - __bfloat162float(h2));
    __nv_bfloat16 l3 = __float2bfloat16(v.w - __bfloat162float(h3));
    unsigned short hu[4] = { *(unsigned short*)&h0, *(unsigned short*)&h1,
                             *(unsigned short*)&h2, *(unsigned short*)&h3 };
    unsigned short lu[4] = { *(unsigned short*)&l0, *(unsigned short*)&l1,
                             *(unsigned short*)&l2, *(unsigned short*)&l3 };
    hi = *(ull*)hu; lo = *(ull*)lu;
}

__global__ __launch_bounds__(256)
void gi_gemm_kernel(const float* __restrict__ A,    // ins  [M, D]
                    const float* __restrict__ Bw,   // Wi   [D, 3H]
                    const float* __restrict__ bias,
                    float* __restrict__ C)          // gi   [M, 3H]
{
    __shared__ __nv_bfloat16 sAh[128 * SAK], sAl[128 * SAK];
    __shared__ __nv_bfloat16 sBh[128 * SAK], sBl[128 * SAK];

    const int tid = threadIdx.x;
    const int n0  = blockIdx.x * 128;   // fast axis -> A tile L2 reuse
    const int m0  = blockIdx.y * 128;
    const int wid = tid >> 5, lane = tid & 31;
    const int wm = (wid & 1) * 64;      // warp m offset
    const int wn = (wid >> 1) * 32;     // warp n offset
    const int g  = lane >> 2;           // mma group row
    const int tg = lane & 3;

    // A staging: 4 passes, thread -> row = p*32 + tid/8, k4 = (tid%8)*4
    const int ar = tid >> 3, ak = (tid & 7) * 4;
    // B staging: thread -> n = tid%128, kb = (tid/128)*16
    const int bn = tid & 127, bkb = (tid >> 7) * 16;

    float acc[4][4][4];
    #pragma unroll
    for (int i = 0; i < 4; i++)
        #pragma unroll
        for (int j = 0; j < 4; j++)
            #pragma unroll
            for (int q = 0; q < 4; q++) acc[i][j][q] = 0.0f;

    // prefetch chunk 0
    float4 av[4];
    float  bv[16];
    #pragma unroll
    for (int p = 0; p < 4; p++)
        av[p] = *(const float4*)(A + (size_t)(m0 + p * 32 + ar) * D_ + ak);
    #pragma unroll
    for (int q = 0; q < 16; q++)
        bv[q] = Bw[(size_t)(bkb + q) * H3_ + n0 + bn];

    for (int kc = 0; kc < D_ / 32; kc++) {
        __syncthreads();
        // store A
        #pragma unroll
        for (int p = 0; p < 4; p++) {
            ull hi, lo; split_f4(av[p], hi, lo);
            *(ull*)&sAh[(p * 32 + ar) * SAK + ak] = hi;
            *(ull*)&sAl[(p * 32 + ar) * SAK + ak] = lo;
        }
        // store B (as [n][k])
        #pragma unroll
        for (int q = 0; q < 4; q++) {
            float4 v = make_float4(bv[q*4], bv[q*4+1], bv[q*4+2], bv[q*4+3]);
            ull hi, lo; split_f4(v, hi, lo);
            *(ull*)&sBh[bn * SAK + bkb + q * 4] = hi;
            *(ull*)&sBl[bn * SAK + bkb + q * 4] = lo;
        }
        __syncthreads();

        // prefetch next chunk
        if (kc + 1 < D_ / 32) {
            int k0 = (kc + 1) * 32;
            #pragma unroll
            for (int p = 0; p < 4; p++)
                av[p] = *(const float4*)(A + (size_t)(m0 + p * 32 + ar) * D_ + k0 + ak);
            #pragma unroll
            for (int q = 0; q < 16; q++)
                bv[q] = Bw[(size_t)(k0 + bkb + q) * H3_ + n0 + bn];
        }

        #pragma unroll
        for (int ks = 0; ks < 2; ks++) {
            const int kb = ks * 16 + tg * 2;
            // B fragments for 4 n-tiles (hi & lo)
            unsigned bh[4][2], bl[4][2];
            #pragma unroll
            for (int ni = 0; ni < 4; ni++) {
                int nrow = (wn + ni * 8 + g) * SAK;
                bh[ni][0] = *(const unsigned*)&sBh[nrow + kb];
                bh[ni][1] = *(const unsigned*)&sBh[nrow + kb + 8];
                bl[ni][0] = *(const unsigned*)&sBl[nrow + kb];
                bl[ni][1] = *(const unsigned*)&sBl[nrow + kb + 8];
            }
            #pragma unroll
            for (int mi = 0; mi < 4; mi++) {
                int r0 = (wm + mi * 16 + g) * SAK;
                int r8 = r0 + 8 * SAK;
                unsigned ah[4], al[4];
                ah[0] = *(const unsigned*)&sAh[r0 + kb];
                ah[1] = *(const unsigned*)&sAh[r8 + kb];
                ah[2] = *(const unsigned*)&sAh[r0 + kb + 8];
                ah[3] = *(const unsigned*)&sAh[r8 + kb + 8];
                al[0] = *(const unsigned*)&sAl[r0 + kb];
                al[1] = *(const unsigned*)&sAl[r8 + kb];
                al[2] = *(const unsigned*)&sAl[r0 + kb + 8];
                al[3] = *(const unsigned*)&sAl[r8 + kb + 8];
                #pragma unroll
                for (int ni = 0; ni < 4; ni++) {
                    mma_bf16(acc[mi][ni], ah, bh[ni]);
                    mma_bf16(acc[mi][ni], al, bh[ni]);
                    mma_bf16(acc[mi][ni], ah, bl[ni]);
                }
            }
        }
    }

    // epilogue: + bias, store
    #pragma unroll
    for (int ni = 0; ni < 4; ni++) {
        int col = n0 + wn + ni * 8 + tg * 2;
        float b0 = bias[col], b1 = bias[col + 1];
        #pragma unroll
        for (int mi = 0; mi < 4; mi++) {
            int row = m0 + wm + mi * 16 + g;
            float2 o0 = make_float2(acc[mi][ni][0] + b0, acc[mi][ni][1] + b1);
            float2 o1 = make_float2(acc[mi][ni][2] + b0, acc[mi][ni][3] + b1);
            *(float2*)(C + (size_t)row * H3_ + col) = o0;
            *(float2*)(C + (size_t)(row + 8) * H3_ + col) = o1;
        }
    }
}

// ===========================================================================
// Per-batch-group barrier: 16 blocks sharing one batch tile
// ===========================================================================
__device__ __forceinline__ void group_sync(int grp)
{
    __syncthreads();
    if (threadIdx.x == 0) {
        unsigned g = g_gen8[grp * 32];
        __threadfence();
        if (atomicAdd(&g_cnt8[grp * 32], 1) == 15) {
            g_cnt8[grp * 32] = 0;
            __threadfence();
            g_gen8[grp * 32] = g + 1;
        } else {
            while (g_gen8[grp * 32] == g) { __nanosleep(32); }
        }
        __threadfence();
    }
    __syncthreads();
}

// ===========================================================================
// Persistent GRU scan. 128 blocks = (8 b-tiles of 32) x (16 h-tiles of 32).
// W slice (192KB) resident in SMEM for all 512 steps. f32x2 FMAs.
// ===========================================================================
#define WS_F2   (512 * 48)
#define HS_STR  68
#define SMEM_BYTES (WS_F2 * 8 + 32 * HS_STR * 4 + 128)

__global__ __launch_bounds__(NTHR, 1)
void gru_scan_kernel(const float* __restrict__ rnn_state,
                     const float* __restrict__ Whrz,
                     const float* __restrict__ Whn,
                     const float* __restrict__ bhn,
                     const float* __restrict__ gi,
                     float* __restrict__ ys)
{
    extern __shared__ char smraw[];
    float2* ws2 = (float2*)smraw;
    float*  hs  = (float*)(smraw + WS_F2 * 8);
    float*  sm  = (float*)(smraw + WS_F2 * 8 + 32 * HS_STR * 4);

    const int tid = threadIdx.x;
    const int bid = blockIdx.x;
    const int hti = bid & 15, bti = bid >> 4;
    const int hb  = hti * 32;
    const int b0  = bti * 32;
    const int th  = tid & 15;
    const int tb  = tid >> 4;
    const int bb0 = tb * 2, bb1 = bb0 + 1;

    for (int i = tid; i < WS_F2; i += NTHR) {
        int k = i / 48, c = i % 48, g = c >> 4, j = (c & 15) * 2;
        const float* src;
        if (g == 0)      src = Whrz + (size_t)k * H2_ + hb + j;
        else if (g == 1) src = Whrz + (size_t)k * H2_ + H_ + hb + j;
        else             src = Whn  + (size_t)k * H_  + hb + j;
        ws2[i] = *(const float2*)src;
    }

    const int s0  = tid,        s1  = tid + NTHR;
    const int lb0 = s0 >> 4,    kq0 = (s0 & 15) * 4;
    const int lb1 = s1 >> 4,    kq1 = (s1 & 15) * 4;

    for (int t = 0; t < T_; t++) {
        const float* hin = (t == 0) ? rnn_state : (ys + (size_t)(t - 1) * B_ * H_);
        if (tid < 32) sm[tid] = g_mask[t * B_ + b0 + tid];

        const float* hrow0 = hin + (size_t)(b0 + lb0) * H_;
        const float* hrow1 = hin + (size_t)(b0 + lb1) * H_;

        float4 p0 = __ldcg((const float4*)(hrow0 + kq0));
        float4 p1 = __ldcg((const float4*)(hrow1 + kq1));

        ull ar0 = 0, ar1 = 0, az0 = 0, az1 = 0, an0 = 0, an1 = 0;

        for (int c = 0; c < 8; c++) {
            __syncthreads();
            float m0 = sm[lb0], m1 = sm[lb1];
            float4 q0 = make_float4(p0.x * m0, p0.y * m0, p0.z * m0, p0.w * m0);
            float4 q1 = make_float4(p1.x * m1, p1.y * m1, p1.z * m1, p1.w * m1);
            *(float4*)&hs[lb0 * HS_STR + kq0] = q0;
            *(float4*)&hs[lb1 * HS_STR + kq1] = q1;
            if (c < 7) {
                p0 = __ldcg((const float4*)(hrow0 + (c + 1) * 64 + kq0));
                p1 = __ldcg((const float4*)(hrow1 + (c + 1) * 64 + kq1));
            }
            __syncthreads();

            const float2* wk = ws2 + (size_t)c * 64 * 48 + th;
            #pragma unroll 8
            for (int kk = 0; kk < 64; kk++) {
                float hv0 = hs[bb0 * HS_STR + kk];
                float hv1 = hs[bb1 * HS_STR + kk];
                ull h0p = pack2(hv0);
                ull h1p = pack2(hv1);
                const float2* w = wk + kk * 48;
                ull wr = *(const ull*)(w);
                ull wz = *(const ull*)(w + 16);
                ull wn = *(const ull*)(w + 32);
                fma2(ar0, h0p, wr); fma2(az0, h0p, wz); fma2(an0, h0p, wn);
                fma2(ar1, h1p, wr); fma2(az1, h1p, wz); fma2(an1, h1p, wn);
            }
        }

        const int hc = hb + th * 2;
        const float2 bh2 = *(const float2*)(bhn + hc);

        #pragma unroll
        for (int r = 0; r < 2; r++) {
            const int bb = (r == 0) ? bb0 : bb1;
            const int b  = b0 + bb;
            const float m = sm[bb];
            float2 cr = unpk(r == 0 ? ar0 : ar1);
            float2 cz = unpk(r == 0 ? az0 : az1);
            float2 cn = unpk(r == 0 ? an0 : an1);

            const float* gib = gi + ((size_t)t * B_ + b) * H3_;
            float2 ir  = *(const float2*)(gib + hc);
            float2 iz  = *(const float2*)(gib + H_ + hc);
            float2 in_ = *(const float2*)(gib + 2 * H_ + hc);
            float2 ho  = __ldcg((const float2*)(hin + (size_t)b * H_ + hc));
            float hm0 = ho.x * m, hm1 = ho.y * m;

            float rg0 = 1.0f / (1.0f + expf(-(ir.x + cr.x)));
            float rg1 = 1.0f / (1.0f + expf(-(ir.y + cr.y)));
            float zg0 = 1.0f / (1.0f + expf(-(iz.x + cz.x)));
            float zg1 = 1.0f / (1.0f + expf(-(iz.y + cz.y)));
            float ng0 = tanhf(in_.x + rg0 * (cn.x + bh2.x));
            float ng1 = tanhf(in_.y + rg1 * (cn.y + bh2.y));

            float2 out;
            out.x = (1.0f - zg0) * ng0 + zg0 * hm0;
            out.y = (1.0f - zg1) * ng1 + zg1 * hm1;
            *(float2*)(ys + ((size_t)t * B_ + b) * H_ + hc) = out;
        }

        group_sync(bti);
    }
}

// ===========================================================================
extern "C" void kernel_launch(void* const* d_in, const int* in_sizes, int n_in,
                              void* d_out, int out_size)
{
    const float* rnn_state = (const float*)d_in[0];
    const float* ins       = (const float*)d_in[1];
    const void*  resets    = d_in[2];
    const float* Wi        = (const float*)d_in[3];
    const float* bi        = (const float*)d_in[4];
    const float* Whrz      = (const float*)d_in[5];
    const float* Whn       = (const float*)d_in[6];
    const float* bhn       = (const float*)d_in[7];

    float* final_h = (float*)d_out;
    float* ys      = (float*)d_out + (size_t)B_ * H_;

    float* gi_ptr = nullptr;
    cudaGetSymbolAddress((void**)&gi_ptr, g_gi);

    cudaFuncSetAttribute(gru_scan_kernel,
                         cudaFuncAttributeMaxDynamicSharedMemorySize, SMEM_BYTES);

    prep_mask_kernel<<<1, 1024>>>(resets);

    // gi = ins @ Wi + bi  (tensor cores, split-bf16)
    gi_gemm_kernel<<<dim3(H3_ / 128, (T_ * B_) / 128), 256>>>(ins, Wi, bi, gi_ptr);

    gru_scan_kernel<<<NBLK, NTHR, SMEM_BYTES>>>(rnn_state, Whrz, Whn, bhn,
                                                gi_ptr, ys);

    cudaMemcpyAsync(final_h, ys + (size_t)(T_ - 1) * B_ * H_,
                    (size_t)B_ * H_ * sizeof(float),
                    cudaMemcpyDeviceToDevice, 0);
}

// round 6
// speedup vs baseline: 3.1501x; 1.1733x over previous
#include <cuda_runtime.h>
#include <cuda_bf16.h>
#include <math.h>
#include <cstdint>

#define T_  512
#define B_  256
#define D_  512
#define H_  512
#define H2_ (2*H_)
#define H3_ (3*H_)

#define NBLK 128
#define NTHR 256

typedef unsigned long long ull;

// ===========================================================================
// Global scratch
// ===========================================================================
__device__ float g_gi[(size_t)T_ * B_ * H3_];       // gi = ins @ Wi + bi
__device__ float g_mask[T_ * B_];
__device__ unsigned g_cnt8[8 * 32];
__device__ volatile unsigned g_gen8[8 * 32];

// ===========================================================================
// f32x2 packed-FMA helpers
// ===========================================================================
__device__ __forceinline__ ull pack2(float x) {
    ull r; unsigned u = __float_as_uint(x);
    asm("mov.b64 %0, {%1, %1};" : "=l"(r) : "r"(u));
    return r;
}
__device__ __forceinline__ void fma2(ull& d, ull a, ull b) {
    asm("fma.rn.f32x2 %0, %1, %2, %0;" : "+l"(d) : "l"(a), "l"(b));
}
__device__ __forceinline__ float2 unpk(ull v) {
    float2 f;
    asm("mov.b64 {%0, %1}, %2;" : "=f"(f.x), "=f"(f.y) : "l"(v));
    return f;
}

// ===========================================================================
// Reset-mask prep
// ===========================================================================
__global__ void prep_mask_kernel(const void* __restrict__ resets)
{
    const int N = T_ * B_;
    const unsigned char* b8 = (const unsigned char*)resets;
    int found = 0;
    for (int i = threadIdx.x; i < N; i += blockDim.x)
        if ((i & 3) && b8[i] == 1) found = 1;
    int is_byte = __syncthreads_or(found);
    if (is_byte) {
        for (int i = threadIdx.x; i < N; i += blockDim.x)
            g_mask[i] = b8[i] ? 0.0f : 1.0f;
    } else {
        const unsigned int* w32 = (const unsigned int*)resets;
        for (int i = threadIdx.x; i < N; i += blockDim.x)
            g_mask[i] = w32[i] ? 0.0f : 1.0f;
    }
}

// ncu alignment dummies (shift scan to capture slot #6)
__global__ void noop_kernel() {}

// ===========================================================================
// gi GEMM: C = ins @ Wi + bi via mma.sync bf16-split (unchanged from R5)
// ===========================================================================
#define SAK 40

__device__ __forceinline__ void mma_bf16(float* c, const unsigned* a,
                                         const unsigned* b) {
    asm volatile(
        "mma.sync.aligned.m16n8k16.row.col.f32.bf16.bf16.f32 "
        "{%0,%1,%2,%3}, {%4,%5,%6,%7}, {%8,%9}, {%0,%1,%2,%3};"
        : "+f"(c[0]), "+f"(c[1]), "+f"(c[2]), "+f"(c[3])
        : "r"(a[0]), "r"(a[1]), "r"(a[2]), "r"(a[3]), "r"(b[0]), "r"(b[1]));
}

__device__ __forceinline__ void split_f4(float4 v, ull& hi, ull& lo) {
    __nv_bfloat16 h0 = __float2bfloat16(v.x);
    __nv_bfloat16 h1 = __float2bfloat16(v.y);
    __nv_bfloat16 h2 = __float2bfloat16(v.z);
    __nv_bfloat16 h3 = __float2bfloat16(v.w);
    __nv_bfloat16 l0 = __float2bfloat16(v.x - __bfloat162float(h0));
    __nv_bfloat16 l1 = __float2bfloat16(v.y - __bfloat162float(h1));
    __nv_bfloat16 l2 = __float2bfloat16(v.z - __bfloat162float(h2));
    __nv_bfloat16 l3 = __float2bfloat16(v.w - __bfloat162float(h3));
    unsigned short hu[4] = { *(unsigned short*)&h0, *(unsigned short*)&h1,
                             *(unsigned short*)&h2, *(unsigned short*)&h3 };
    unsigned short lu[4] = { *(unsigned short*)&l0, *(unsigned short*)&l1,
                             *(unsigned short*)&l2, *(unsigned short*)&l3 };
    hi = *(ull*)hu; lo = *(ull*)lu;
}

__global__ __launch_bounds__(256)
void gi_gemm_kernel(const float* __restrict__ A,
                    const float* __restrict__ Bw,
                    const float* __restrict__ bias,
                    float* __restrict__ C)
{
    __shared__ __nv_bfloat16 sAh[128 * SAK], sAl[128 * SAK];
    __shared__ __nv_bfloat16 sBh[128 * SAK], sBl[128 * SAK];

    const int tid = threadIdx.x;
    const int n0  = blockIdx.x * 128;
    const int m0  = blockIdx.y * 128;
    const int wid = tid >> 5, lane = tid & 31;
    const int wm = (wid & 1) * 64;
    const int wn = (wid >> 1) * 32;
    const int g  = lane >> 2;
    const int tg = lane & 3;

    const int ar = tid >> 3, ak = (tid & 7) * 4;
    const int bn = tid & 127, bkb = (tid >> 7) * 16;

    float acc[4][4][4];
    #pragma unroll
    for (int i = 0; i < 4; i++)
        #pragma unroll
        for (int j = 0; j < 4; j++)
            #pragma unroll
            for (int q = 0; q < 4; q++) acc[i][j][q] = 0.0f;

    float4 av[4];
    float  bv[16];
    #pragma unroll
    for (int p = 0; p < 4; p++)
        av[p] = *(const float4*)(A + (size_t)(m0 + p * 32 + ar) * D_ + ak);
    #pragma unroll
    for (int q = 0; q < 16; q++)
        bv[q] = Bw[(size_t)(bkb + q) * H3_ + n0 + bn];

    for (int kc = 0; kc < D_ / 32; kc++) {
        __syncthreads();
        #pragma unroll
        for (int p = 0; p < 4; p++) {
            ull hi, lo; split_f4(av[p], hi, lo);
            *(ull*)&sAh[(p * 32 + ar) * SAK + ak] = hi;
            *(ull*)&sAl[(p * 32 + ar) * SAK + ak] = lo;
        }
        #pragma unroll
        for (int q = 0; q < 4; q++) {
            float4 v = make_float4(bv[q*4], bv[q*4+1], bv[q*4+2], bv[q*4+3]);
            ull hi, lo; split_f4(v, hi, lo);
            *(ull*)&sBh[bn * SAK + bkb + q * 4] = hi;
            *(ull*)&sBl[bn * SAK + bkb + q * 4] = lo;
        }
        __syncthreads();

        if (kc + 1 < D_ / 32) {
            int k0 = (kc + 1) * 32;
            #pragma unroll
            for (int p = 0; p < 4; p++)
                av[p] = *(const float4*)(A + (size_t)(m0 + p * 32 + ar) * D_ + k0 + ak);
            #pragma unroll
            for (int q = 0; q < 16; q++)
                bv[q] = Bw[(size_t)(k0 + bkb + q) * H3_ + n0 + bn];
        }

        #pragma unroll
        for (int ks = 0; ks < 2; ks++) {
            const int kb = ks * 16 + tg * 2;
            unsigned bh[4][2], bl[4][2];
            #pragma unroll
            for (int ni = 0; ni < 4; ni++) {
                int nrow = (wn + ni * 8 + g) * SAK;
                bh[ni][0] = *(const unsigned*)&sBh[nrow + kb];
                bh[ni][1] = *(const unsigned*)&sBh[nrow + kb + 8];
                bl[ni][0] = *(const unsigned*)&sBl[nrow + kb];
                bl[ni][1] = *(const unsigned*)&sBl[nrow + kb + 8];
            }
            #pragma unroll
            for (int mi = 0; mi < 4; mi++) {
                int r0 = (wm + mi * 16 + g) * SAK;
                int r8 = r0 + 8 * SAK;
                unsigned ah[4], al[4];
                ah[0] = *(const unsigned*)&sAh[r0 + kb];
                ah[1] = *(const unsigned*)&sAh[r8 + kb];
                ah[2] = *(const unsigned*)&sAh[r0 + kb + 8];
                ah[3] = *(const unsigned*)&sAh[r8 + kb + 8];
                al[0] = *(const unsigned*)&sAl[r0 + kb];
                al[1] = *(const unsigned*)&sAl[r8 + kb];
                al[2] = *(const unsigned*)&sAl[r0 + kb + 8];
                al[3] = *(const unsigned*)&sAl[r8 + kb + 8];
                #pragma unroll
                for (int ni = 0; ni < 4; ni++) {
                    mma_bf16(acc[mi][ni], ah, bh[ni]);
                    mma_bf16(acc[mi][ni], al, bh[ni]);
                    mma_bf16(acc[mi][ni], ah, bl[ni]);
                }
            }
        }
    }

    #pragma unroll
    for (int ni = 0; ni < 4; ni++) {
        int col = n0 + wn + ni * 8 + tg * 2;
        float b0 = bias[col], b1 = bias[col + 1];
        #pragma unroll
        for (int mi = 0; mi < 4; mi++) {
            int row = m0 + wm + mi * 16 + g;
            float2 o0 = make_float2(acc[mi][ni][0] + b0, acc[mi][ni][1] + b1);
            float2 o1 = make_float2(acc[mi][ni][2] + b0, acc[mi][ni][3] + b1);
            *(float2*)(C + (size_t)row * H3_ + col) = o0;
            *(float2*)(C + (size_t)(row + 8) * H3_ + col) = o1;
        }
    }
}

// ===========================================================================
// Per-batch-group barrier: 16 blocks sharing one batch tile
// ===========================================================================
__device__ __forceinline__ void group_sync(int grp)
{
    __syncthreads();
    if (threadIdx.x == 0) {
        unsigned g = g_gen8[grp * 32];
        __threadfence();
        if (atomicAdd(&g_cnt8[grp * 32], 1) == 15) {
            g_cnt8[grp * 32] = 0;
            __threadfence();
            g_gen8[grp * 32] = g + 1;
        } else {
            while (g_gen8[grp * 32] == g) { __nanosleep(32); }
        }
        __threadfence();
    }
    __syncthreads();
}

// ===========================================================================
// Persistent GRU scan, v2: k-split 2-way, 4 b-rows/thread, hs transposed.
// Block = 32b x 32h (x3 gates), W slice 192KB resident.
// tid: kh = tid>>7 (k half), t7 = tid&127, th = t7&15 (h-pair), tb = t7>>4.
// Compute: each thread 4b x 2h x 3g over its 256-k half; smem reduction.
// hs: per half [64][36] floats, [k][b] layout (LDS.128 over 4 b-rows).
// Named barriers per half; full syncs only for the reduction + group barrier.
// ===========================================================================
#define HSW 36
#define HS_HALF (64 * HSW)                       // floats per half buffer
#define WS_F2   (512 * 48)
#define SMEM_BYTES (WS_F2 * 8 + 2 * HS_HALF * 4 + 256)
#define SCR_STR 26

__device__ __forceinline__ void half_bar(int kh) {
    asm volatile("bar.sync %0, 128;" :: "r"(1 + kh) : "memory");
}

__global__ __launch_bounds__(NTHR, 1)
void gru_scan_kernel(const float* __restrict__ rnn_state,
                     const float* __restrict__ Whrz,
                     const float* __restrict__ Whn,
                     const float* __restrict__ bhn,
                     const float* __restrict__ gi,
                     float* __restrict__ ys)
{
    extern __shared__ char smraw[];
    float2* ws2  = (float2*)smraw;                         // [512][48]
    float*  hsA  = (float*)(smraw + WS_F2 * 8);            // 2 x [64][36]
    float*  smk  = (float*)(smraw + WS_F2 * 8 + 2 * HS_HALF * 4); // [2][32]
    float*  scratch = hsA;                                 // epilogue alias

    const int tid = threadIdx.x;
    const int bid = blockIdx.x;
    const int hti = bid & 15, bti = bid >> 4;
    const int hb  = hti * 32;
    const int b0  = bti * 32;
    const int kh  = tid >> 7;
    const int t7  = tid & 127;
    const int th  = t7 & 15;
    const int tb  = t7 >> 4;          // 0..7 (b-quad)
    const int kbase = kh * 256;
    float* hs_ = hsA + kh * HS_HALF;
    float* smh = smk + kh * 32;

    // loader mapping: k4 = (t7&15)*4, rows = tb*4 .. +3 (same as compute quad)
    const int k4 = th * 4;

    // ---- resident W slice (same layout as before)
    for (int i = tid; i < WS_F2; i += NTHR) {
        int k = i / 48, c = i % 48, g = c >> 4, j = (c & 15) * 2;
        const float* src;
        if (g == 0)      src = Whrz + (size_t)k * H2_ + hb + j;
        else if (g == 1) src = Whrz + (size_t)k * H2_ + H_ + hb + j;
        else             src = Whn  + (size_t)k * H_  + hb + j;
        ws2[i] = *(const float2*)src;
    }

    for (int t = 0; t < T_; t++) {
        const float* hin = (t == 0) ? rnn_state : (ys + (size_t)(t - 1) * B_ * H_);
        if (t7 < 32) smh[t7] = g_mask[t * B_ + b0 + t7];

        const float* r0p = hin + (size_t)(b0 + tb * 4 + 0) * H_ + kbase + k4;
        const float* r1p = r0p + H_;
        const float* r2p = r1p + H_;
        const float* r3p = r2p + H_;

        float4 v0 = __ldcg((const float4*)r0p);
        float4 v1 = __ldcg((const float4*)r1p);
        float4 v2 = __ldcg((const float4*)r2p);
        float4 v3 = __ldcg((const float4*)r3p);

        ull ar[4] = {0,0,0,0}, az[4] = {0,0,0,0}, an[4] = {0,0,0,0};

        half_bar(kh);   // smk visible; hs free (prev step done)

        for (int cc = 0; cc < 4; cc++) {
            // transpose-store chunk: STS.128 along b at each k
            {
                float m0 = smh[tb * 4 + 0], m1 = smh[tb * 4 + 1];
                float m2 = smh[tb * 4 + 2], m3 = smh[tb * 4 + 3];
                float* d = hs_ + k4 * HSW + tb * 4;
                *(float4*)(d)           = make_float4(v0.x*m0, v1.x*m1, v2.x*m2, v3.x*m3);
                *(float4*)(d + HSW)     = make_float4(v0.y*m0, v1.y*m1, v2.y*m2, v3.y*m3);
                *(float4*)(d + 2*HSW)   = make_float4(v0.z*m0, v1.z*m1, v2.z*m2, v3.z*m3);
                *(float4*)(d + 3*HSW)   = make_float4(v0.w*m0, v1.w*m1, v2.w*m2, v3.w*m3);
            }
            half_bar(kh);   // hs chunk ready

            if (cc < 3) {   // prefetch next chunk (overlaps compute)
                int off = (cc + 1) * 64;
                v0 = __ldcg((const float4*)(r0p + off));
                v1 = __ldcg((const float4*)(r1p + off));
                v2 = __ldcg((const float4*)(r2p + off));
                v3 = __ldcg((const float4*)(r3p + off));
            }

            const float2* wp = ws2 + (size_t)(kbase + cc * 64) * 48 + th;
            const float* hq = hs_ + tb * 4;
            #pragma unroll 8
            for (int kk = 0; kk < 64; kk++) {
                float4 hv = *(const float4*)(hq + kk * HSW);
                ull h0 = pack2(hv.x), h1 = pack2(hv.y);
                ull h2 = pack2(hv.z), h3 = pack2(hv.w);
                ull wr = *(const ull*)(wp);
                ull wz = *(const ull*)(wp + 16);
                ull wn = *(const ull*)(wp + 32);
                fma2(ar[0], h0, wr); fma2(ar[1], h1, wr);
                fma2(ar[2], h2, wr); fma2(ar[3], h3, wr);
                fma2(az[0], h0, wz); fma2(az[1], h1, wz);
                fma2(az[2], h2, wz); fma2(az[3], h3, wz);
                fma2(an[0], h0, wn); fma2(an[1], h1, wn);
                fma2(an[2], h2, wn); fma2(an[3], h3, wn);
                wp += 48;
            }
            half_bar(kh);   // compute done -> hs reusable
        }

        // ---- cross-half reduction + gates
        __syncthreads();
        if (kh == 1) {
            float* sc = scratch + t7 * SCR_STR;
            #pragma unroll
            for (int j = 0; j < 4; j++) {
                *(float2*)(sc + j * 2)      = unpk(ar[j]);
                *(float2*)(sc + 8 + j * 2)  = unpk(az[j]);
                *(float2*)(sc + 16 + j * 2) = unpk(an[j]);
            }
        }
        __syncthreads();
        if (kh == 0) {
            const float* sc = scratch + t7 * SCR_STR;
            const int hc = hb + th * 2;
            const float2 bh2 = *(const float2*)(bhn + hc);
            #pragma unroll
            for (int j = 0; j < 4; j++) {
                const int b = b0 + tb * 4 + j;
                const float m = smh[tb * 4 + j];
                float2 cr = unpk(ar[j]);
                float2 cz = unpk(az[j]);
                float2 cn = unpk(an[j]);
                float2 s;
                s = *(const float2*)(sc + j * 2);      cr.x += s.x; cr.y += s.y;
                s = *(const float2*)(sc + 8 + j * 2);  cz.x += s.x; cz.y += s.y;
                s = *(const float2*)(sc + 16 + j * 2); cn.x += s.x; cn.y += s.y;

                const float* gib = gi + ((size_t)t * B_ + b) * H3_;
                float2 ir  = *(const float2*)(gib + hc);
                float2 iz  = *(const float2*)(gib + H_ + hc);
                float2 in_ = *(const float2*)(gib + 2 * H_ + hc);
                float2 ho  = __ldcg((const float2*)(hin + (size_t)b * H_ + hc));
                float hm0 = ho.x * m, hm1 = ho.y * m;

                float rg0 = 1.0f / (1.0f + expf(-(ir.x + cr.x)));
                float rg1 = 1.0f / (1.0f + expf(-(ir.y + cr.y)));
                float zg0 = 1.0f / (1.0f + expf(-(iz.x + cz.x)));
                float zg1 = 1.0f / (1.0f + expf(-(iz.y + cz.y)));
                float ng0 = tanhf(in_.x + rg0 * (cn.x + bh2.x));
                float ng1 = tanhf(in_.y + rg1 * (cn.y + bh2.y));

                float2 out;
                out.x = (1.0f - zg0) * ng0 + zg0 * hm0;
                out.y = (1.0f - zg1) * ng1 + zg1 * hm1;
                *(float2*)(ys + ((size_t)t * B_ + b) * H_ + hc) = out;
            }
        }

        group_sync(bti);
    }
}

// ===========================================================================
extern "C" void kernel_launch(void* const* d_in, const int* in_sizes, int n_in,
                              void* d_out, int out_size)
{
    const float* rnn_state = (const float*)d_in[0];
    const float* ins       = (const float*)d_in[1];
    const void*  resets    = d_in[2];
    const float* Wi        = (const float*)d_in[3];
    const float* bi        = (const float*)d_in[4];
    const float* Whrz      = (const float*)d_in[5];
    const float* Whn       = (const float*)d_in[6];
    const float* bhn       = (const float*)d_in[7];

    float* final_h = (float*)d_out;
    float* ys      = (float*)d_out + (size_t)B_ * H_;

    float* gi_ptr = nullptr;
    cudaGetSymbolAddress((void**)&gi_ptr, g_gi);

    cudaFuncSetAttribute(gru_scan_kernel,
                         cudaFuncAttributeMaxDynamicSharedMemorySize, SMEM_BYTES);

    prep_mask_kernel<<<1, 1024>>>(resets);

    gi_gemm_kernel<<<dim3(H3_ / 128, (T_ * B_) / 128), 256>>>(ins, Wi, bi, gi_ptr);

    // ncu alignment: puts gru_scan_kernel at launch #6 (-s 5 -c 1 capture slot)
    noop_kernel<<<1, 32>>>();
    noop_kernel<<<1, 32>>>();
    noop_kernel<<<1, 32>>>();

    gru_scan_kernel<<<NBLK, NTHR, SMEM_BYTES>>>(rnn_state, Whrz, Whn, bhn,
                                                gi_ptr, ys);

    cudaMemcpyAsync(final_h, ys + (size_t)(T_ - 1) * B_ * H_,
                    (size_t)B_ * H_ * sizeof(float),
                    cudaMemcpyDeviceToDevice, 0);
}

// round 7
// speedup vs baseline: 4.9139x; 1.5599x over previous
#include <cuda_runtime.h>
#include <cuda_bf16.h>
#include <math.h>
#include <cstdint>

#define T_  512
#define B_  256
#define D_  512
#define H_  512
#define H2_ (2*H_)
#define H3_ (3*H_)

#define NBLK 128
#define NTHR 256

typedef unsigned long long ull;

// ===========================================================================
// Global scratch
// ===========================================================================
__device__ float g_gi[(size_t)T_ * B_ * H3_];       // gi = ins @ Wi + bi
__device__ float g_mask[T_ * B_];
__device__ unsigned g_cnt8[8 * 32];
__device__ volatile unsigned g_gen8[8 * 32];

// ===========================================================================
// helpers
// ===========================================================================
__device__ __forceinline__ void mma_bf16(float* c, const unsigned* a,
                                         const unsigned* b) {
    asm volatile(
        "mma.sync.aligned.m16n8k16.row.col.f32.bf16.bf16.f32 "
        "{%0,%1,%2,%3}, {%4,%5,%6,%7}, {%8,%9}, {%0,%1,%2,%3};"
        : "+f"(c[0]), "+f"(c[1]), "+f"(c[2]), "+f"(c[3])
        : "r"(a[0]), "r"(a[1]), "r"(a[2]), "r"(a[3]), "r"(b[0]), "r"(b[1]));
}

__device__ __forceinline__ void split_f4(float4 v, ull& hi, ull& lo) {
    __nv_bfloat16 h0 = __float2bfloat16(v.x);
    __nv_bfloat16 h1 = __float2bfloat16(v.y);
    __nv_bfloat16 h2 = __float2bfloat16(v.z);
    __nv_bfloat16 h3 = __float2bfloat16(v.w);
    __nv_bfloat16 l0 = __float2bfloat16(v.x - __bfloat162float(h0));
    __nv_bfloat16 l1 = __float2bfloat16(v.y - __bfloat162float(h1));
    __nv_bfloat16 l2 = __float2bfloat16(v.z - __bfloat162float(h2));
    __nv_bfloat16 l3 = __float2bfloat16(v.w - __bfloat162float(h3));
    unsigned short hu[4] = { *(unsigned short*)&h0, *(unsigned short*)&h1,
                             *(unsigned short*)&h2, *(unsigned short*)&h3 };
    unsigned short lu[4] = { *(unsigned short*)&l0, *(unsigned short*)&l1,
                             *(unsigned short*)&l2, *(unsigned short*)&l3 };
    hi = *(ull*)hu; lo = *(ull*)lu;
}

__device__ __forceinline__ void split_f1(float v, unsigned short& hi,
                                         unsigned short& lo) {
    __nv_bfloat16 h = __float2bfloat16(v);
    __nv_bfloat16 l = __float2bfloat16(v - __bfloat162float(h));
    hi = *(unsigned short*)&h;
    lo = *(unsigned short*)&l;
}

// ===========================================================================
// Reset-mask prep
// ===========================================================================
__global__ void prep_mask_kernel(const void* __restrict__ resets)
{
    const int N = T_ * B_;
    const unsigned char* b8 = (const unsigned char*)resets;
    int found = 0;
    for (int i = threadIdx.x; i < N; i += blockDim.x)
        if ((i & 3) && b8[i] == 1) found = 1;
    int is_byte = __syncthreads_or(found);
    if (is_byte) {
        for (int i = threadIdx.x; i < N; i += blockDim.x)
            g_mask[i] = b8[i] ? 0.0f : 1.0f;
    } else {
        const unsigned int* w32 = (const unsigned int*)resets;
        for (int i = threadIdx.x; i < N; i += blockDim.x)
            g_mask[i] = w32[i] ? 0.0f : 1.0f;
    }
}

__global__ void noop_kernel() {}

// ===========================================================================
// gi GEMM (unchanged from R5 — proven)
// ===========================================================================
#define SAK 40

__global__ __launch_bounds__(256)
void gi_gemm_kernel(const float* __restrict__ A,
                    const float* __restrict__ Bw,
                    const float* __restrict__ bias,
                    float* __restrict__ C)
{
    __shared__ __nv_bfloat16 sAh[128 * SAK], sAl[128 * SAK];
    __shared__ __nv_bfloat16 sBh[128 * SAK], sBl[128 * SAK];

    const int tid = threadIdx.x;
    const int n0  = blockIdx.x * 128;
    const int m0  = blockIdx.y * 128;
    const int wid = tid >> 5, lane = tid & 31;
    const int wm = (wid & 1) * 64;
    const int wn = (wid >> 1) * 32;
    const int g  = lane >> 2;
    const int tg = lane & 3;

    const int ar = tid >> 3, ak = (tid & 7) * 4;
    const int bn = tid & 127, bkb = (tid >> 7) * 16;

    float acc[4][4][4];
    #pragma unroll
    for (int i = 0; i < 4; i++)
        #pragma unroll
        for (int j = 0; j < 4; j++)
            #pragma unroll
            for (int q = 0; q < 4; q++) acc[i][j][q] = 0.0f;

    float4 av[4];
    float  bv[16];
    #pragma unroll
    for (int p = 0; p < 4; p++)
        av[p] = *(const float4*)(A + (size_t)(m0 + p * 32 + ar) * D_ + ak);
    #pragma unroll
    for (int q = 0; q < 16; q++)
        bv[q] = Bw[(size_t)(bkb + q) * H3_ + n0 + bn];

    for (int kc = 0; kc < D_ / 32; kc++) {
        __syncthreads();
        #pragma unroll
        for (int p = 0; p < 4; p++) {
            ull hi, lo; split_f4(av[p], hi, lo);
            *(ull*)&sAh[(p * 32 + ar) * SAK + ak] = hi;
            *(ull*)&sAl[(p * 32 + ar) * SAK + ak] = lo;
        }
        #pragma unroll
        for (int q = 0; q < 4; q++) {
            float4 v = make_float4(bv[q*4], bv[q*4+1], bv[q*4+2], bv[q*4+3]);
            ull hi, lo; split_f4(v, hi, lo);
            *(ull*)&sBh[bn * SAK + bkb + q * 4] = hi;
            *(ull*)&sBl[bn * SAK + bkb + q * 4] = lo;
        }
        __syncthreads();

        if (kc + 1 < D_ / 32) {
            int k0 = (kc + 1) * 32;
            #pragma unroll
            for (int p = 0; p < 4; p++)
                av[p] = *(const float4*)(A + (size_t)(m0 + p * 32 + ar) * D_ + k0 + ak);
            #pragma unroll
            for (int q = 0; q < 16; q++)
                bv[q] = Bw[(size_t)(k0 + bkb + q) * H3_ + n0 + bn];
        }

        #pragma unroll
        for (int ks = 0; ks < 2; ks++) {
            const int kb = ks * 16 + tg * 2;
            unsigned bh[4][2], bl[4][2];
            #pragma unroll
            for (int ni = 0; ni < 4; ni++) {
                int nrow = (wn + ni * 8 + g) * SAK;
                bh[ni][0] = *(const unsigned*)&sBh[nrow + kb];
                bh[ni][1] = *(const unsigned*)&sBh[nrow + kb + 8];
                bl[ni][0] = *(const unsigned*)&sBl[nrow + kb];
                bl[ni][1] = *(const unsigned*)&sBl[nrow + kb + 8];
            }
            #pragma unroll
            for (int mi = 0; mi < 4; mi++) {
                int r0 = (wm + mi * 16 + g) * SAK;
                int r8 = r0 + 8 * SAK;
                unsigned ah[4], al[4];
                ah[0] = *(const unsigned*)&sAh[r0 + kb];
                ah[1] = *(const unsigned*)&sAh[r8 + kb];
                ah[2] = *(const unsigned*)&sAh[r0 + kb + 8];
                ah[3] = *(const unsigned*)&sAh[r8 + kb + 8];
                al[0] = *(const unsigned*)&sAl[r0 + kb];
                al[1] = *(const unsigned*)&sAl[r8 + kb];
                al[2] = *(const unsigned*)&sAl[r0 + kb + 8];
                al[3] = *(const unsigned*)&sAl[r8 + kb + 8];
                #pragma unroll
                for (int ni = 0; ni < 4; ni++) {
                    mma_bf16(acc[mi][ni], ah, bh[ni]);
                    mma_bf16(acc[mi][ni], al, bh[ni]);
                    mma_bf16(acc[mi][ni], ah, bl[ni]);
                }
            }
        }
    }

    #pragma unroll
    for (int ni = 0; ni < 4; ni++) {
        int col = n0 + wn + ni * 8 + tg * 2;
        float b0 = bias[col], b1 = bias[col + 1];
        #pragma unroll
        for (int mi = 0; mi < 4; mi++) {
            int row = m0 + wm + mi * 16 + g;
            float2 o0 = make_float2(acc[mi][ni][0] + b0, acc[mi][ni][1] + b1);
            float2 o1 = make_float2(acc[mi][ni][2] + b0, acc[mi][ni][3] + b1);
            *(float2*)(C + (size_t)row * H3_ + col) = o0;
            *(float2*)(C + (size_t)(row + 8) * H3_ + col) = o1;
        }
    }
}

// ===========================================================================
// Per-batch-group barrier (16 blocks / batch tile)
// ===========================================================================
__device__ __forceinline__ void group_sync(int grp)
{
    __syncthreads();
    if (threadIdx.x == 0) {
        unsigned g = g_gen8[grp * 32];
        __threadfence();
        if (atomicAdd(&g_cnt8[grp * 32], 1) == 15) {
            g_cnt8[grp * 32] = 0;
            __threadfence();
            g_gen8[grp * 32] = g + 1;
        } else {
            while (g_gen8[grp * 32] == g) { __nanosleep(32); }
        }
        __threadfence();
    }
    __syncthreads();
}

// ===========================================================================
// Persistent GRU scan, v3: tensor-core recurrent GEMM (split-bf16 mma.sync).
// Block = 32 batch x 32 h (x3 gates) = [96n x 512k] GEMM vs h[32m x 512k].
// W resident in SMEM as bf16 hi+lo, [96][WKS] (~199.7KB).
// h converted per 64-k chunk into bf16 hi/lo staging (9.2KB x2).
// Epilogue: acc -> SMEM transpose (aliases staging) -> fused gates.
// Warp layout: 8 warps = 2 m-groups(16) x 4 n-groups(24).
// ===========================================================================
#define WKS  520                       // W k-stride (elems, pad 8)
#define HKS  72                        // hs chunk k-stride (elems, pad 8)
#define OFF_WLO  99840                 // bytes: 96*520*2
#define OFF_HS   199680                // bytes: 2*OFF_WLO
#define HSBUF    9216                  // bytes per hs buffer (Ah 4608 + Al 4608)
#define OFF_MASK (OFF_HS + 2*HSBUF)    // 218112
#define GOUT_STR 100                   // gout row stride (floats)
#define SCAN_SMEM (OFF_MASK + 256)     // 218368 bytes

__global__ __launch_bounds__(NTHR, 1)
void gru_scan_kernel(const float* __restrict__ rnn_state,
                     const float* __restrict__ Whrz,
                     const float* __restrict__ Whn,
                     const float* __restrict__ bhn,
                     const float* __restrict__ gi,
                     float* __restrict__ ys)
{
    extern __shared__ char smraw[];
    __nv_bfloat16* Whi = (__nv_bfloat16*)smraw;
    __nv_bfloat16* Wlo = (__nv_bfloat16*)(smraw + OFF_WLO);
    float* mask_sm = (float*)(smraw + OFF_MASK);
    float* gout    = (float*)(smraw + OFF_HS);       // alias of hs buffers

    const int tid = threadIdx.x;
    const int bid = blockIdx.x;
    const int hti = bid & 15, bti = bid >> 4;
    const int hb  = hti * 32;
    const int b0  = bti * 32;

    const int wid = tid >> 5, lane = tid & 31;
    const int wm  = (wid & 1) * 16;         // warp m offset (batch)
    const int wn  = (wid >> 1) * 24;        // warp n offset (gate cols)
    const int g   = lane >> 2;
    const int tg  = lane & 3;

    // hs conversion mapping: slots s = tid, tid+256 -> m = s>>4, kq = (s&15)*4
    const int cm0 = tid >> 4;               // 0..15
    const int cm1 = 16 + cm0;
    const int ckq = (tid & 15) * 4;

    // epilogue mapping: b = tid>>3, h4 = (tid&7)*4
    const int eb  = tid >> 3;
    const int eh4 = (tid & 7) * 4;

    // ---- one-time: convert W slice to bf16 hi/lo resident [96][WKS]
    // n: 0..31 -> Whrz[:, hb+n] (r); 32..63 -> Whrz[:, H+hb+n-32] (z);
    // 64..95 -> Whn[:, hb+n-64]
    for (int i = tid; i < 96 * 128; i += NTHR) {
        int n = i >> 7, kq = (i & 127) * 4;
        int gate = n >> 5, hcol = hb + (n & 31);
        const float* src;
        int stride;
        if (gate == 0)      { src = Whrz + hcol;        stride = H2_; }
        else if (gate == 1) { src = Whrz + H_ + hcol;   stride = H2_; }
        else                { src = Whn + hcol;         stride = H_;  }
        unsigned short hv[4], lv[4];
        #pragma unroll
        for (int j = 0; j < 4; j++)
            split_f1(src[(size_t)(kq + j) * stride], hv[j], lv[j]);
        *(ull*)&Whi[n * WKS + kq] = *(ull*)hv;
        *(ull*)&Wlo[n * WKS + kq] = *(ull*)lv;
    }

    // bias for epilogue (invariant)
    const float4 bh4 = *(const float4*)(bhn + hb + eh4);

    for (int t = 0; t < T_; t++) {
        const float* hin = (t == 0) ? rnn_state : (ys + (size_t)(t - 1) * B_ * H_);

        if (tid < 32) mask_sm[tid] = g_mask[t * B_ + b0 + tid];

        // prefetch: epilogue inputs (hide DRAM latency under the GEMM)
        const float* gib = gi + ((size_t)t * B_ + b0 + eb) * H3_ + hb + eh4;
        float4 ir4 = __ldcg((const float4*)(gib));
        float4 iz4 = __ldcg((const float4*)(gib + H_));
        float4 in4 = __ldcg((const float4*)(gib + 2 * H_));
        float4 ho4 = __ldcg((const float4*)(hin + (size_t)(b0 + eb) * H_ + hb + eh4));

        // prefetch chunk 0 of h
        const float* hr0 = hin + (size_t)(b0 + cm0) * H_ + ckq;
        const float* hr1 = hin + (size_t)(b0 + cm1) * H_ + ckq;
        float4 v0 = __ldcg((const float4*)hr0);
        float4 v1 = __ldcg((const float4*)hr1);

        float acc[3][4];
        #pragma unroll
        for (int ni = 0; ni < 3; ni++)
            #pragma unroll
            for (int q = 0; q < 4; q++) acc[ni][q] = 0.0f;

        for (int c = 0; c < 8; c++) {
            __syncthreads();                 // hs buffer free / mask ready
            __nv_bfloat16* hsAh = (__nv_bfloat16*)(smraw + OFF_HS + (c & 1) * HSBUF);
            __nv_bfloat16* hsAl = hsAh + 2304;   // 4608 bytes

            // convert + store this chunk (mask applied pre-split)
            {
                float m0 = mask_sm[cm0], m1 = mask_sm[cm1];
                ull hi, lo;
                split_f4(make_float4(v0.x*m0, v0.y*m0, v0.z*m0, v0.w*m0), hi, lo);
                *(ull*)&hsAh[cm0 * HKS + ckq] = hi;
                *(ull*)&hsAl[cm0 * HKS + ckq] = lo;
                split_f4(make_float4(v1.x*m1, v1.y*m1, v1.z*m1, v1.w*m1), hi, lo);
                *(ull*)&hsAh[cm1 * HKS + ckq] = hi;
                *(ull*)&hsAl[cm1 * HKS + ckq] = lo;
            }
            __syncthreads();                 // hs ready

            if (c < 7) {                     // prefetch next chunk
                int off = (c + 1) * 64;
                v0 = __ldcg((const float4*)(hr0 + off));
                v1 = __ldcg((const float4*)(hr1 + off));
            }

            #pragma unroll
            for (int ks = 0; ks < 4; ks++) {
                const int kw = c * 64 + ks * 16 + tg * 2;   // W k index
                const int kl = ks * 16 + tg * 2;            // hs k index
                unsigned bh[3][2], bl[3][2];
                #pragma unroll
                for (int ni = 0; ni < 3; ni++) {
                    int nrow = (wn + ni * 8 + g) * WKS;
                    bh[ni][0] = *(const unsigned*)&Whi[nrow + kw];
                    bh[ni][1] = *(const unsigned*)&Whi[nrow + kw + 8];
                    bl[ni][0] = *(const unsigned*)&Wlo[nrow + kw];
                    bl[ni][1] = *(const unsigned*)&Wlo[nrow + kw + 8];
                }
                int r0 = (wm + g) * HKS + kl;
                int r8 = r0 + 8 * HKS;
                unsigned ah[4], al[4];
                ah[0] = *(const unsigned*)&hsAh[r0];
                ah[1] = *(const unsigned*)&hsAh[r8];
                ah[2] = *(const unsigned*)&hsAh[r0 + 8];
                ah[3] = *(const unsigned*)&hsAh[r8 + 8];
                al[0] = *(const unsigned*)&hsAl[r0];
                al[1] = *(const unsigned*)&hsAl[r8];
                al[2] = *(const unsigned*)&hsAl[r0 + 8];
                al[3] = *(const unsigned*)&hsAl[r8 + 8];
                #pragma unroll
                for (int ni = 0; ni < 3; ni++) {
                    mma_bf16(acc[ni], ah, bh[ni]);
                    mma_bf16(acc[ni], al, bh[ni]);
                    mma_bf16(acc[ni], ah, bl[ni]);
                }
            }
        }

        // ---- epilogue: transpose acc through SMEM, fused gates
        __syncthreads();                     // all compute done -> gout aliasable
        #pragma unroll
        for (int ni = 0; ni < 3; ni++) {
            int col = wn + ni * 8 + tg * 2;
            *(float2*)&gout[(wm + g) * GOUT_STR + col] =
                make_float2(acc[ni][0], acc[ni][1]);
            *(float2*)&gout[(wm + g + 8) * GOUT_STR + col] =
                make_float2(acc[ni][2], acc[ni][3]);
        }
        __syncthreads();

        {
            const float m = mask_sm[eb];
            float4 cr = *(const float4*)&gout[eb * GOUT_STR + eh4];
            float4 cz = *(const float4*)&gout[eb * GOUT_STR + 32 + eh4];
            float4 cn = *(const float4*)&gout[eb * GOUT_STR + 64 + eh4];

            float hm[4] = { ho4.x * m, ho4.y * m, ho4.z * m, ho4.w * m };
            float irv[4] = { ir4.x, ir4.y, ir4.z, ir4.w };
            float izv[4] = { iz4.x, iz4.y, iz4.z, iz4.w };
            float inv[4] = { in4.x, in4.y, in4.z, in4.w };
            float crv[4] = { cr.x, cr.y, cr.z, cr.w };
            float czv[4] = { cz.x, cz.y, cz.z, cz.w };
            float cnv[4] = { cn.x, cn.y, cn.z, cn.w };
            float bhv[4] = { bh4.x, bh4.y, bh4.z, bh4.w };

            float out[4];
            #pragma unroll
            for (int j = 0; j < 4; j++) {
                float r = 1.0f / (1.0f + __expf(-(irv[j] + crv[j])));
                float z = 1.0f / (1.0f + __expf(-(izv[j] + czv[j])));
                float e = __expf(2.0f * (inv[j] + r * (cnv[j] + bhv[j])));
                float n = __fdividef(e - 1.0f, e + 1.0f);
                out[j] = (1.0f - z) * n + z * hm[j];
            }
            *(float4*)(ys + ((size_t)t * B_ + b0 + eb) * H_ + hb + eh4) =
                make_float4(out[0], out[1], out[2], out[3]);
        }

        group_sync(bti);
    }
}

// ===========================================================================
extern "C" void kernel_launch(void* const* d_in, const int* in_sizes, int n_in,
                              void* d_out, int out_size)
{
    const float* rnn_state = (const float*)d_in[0];
    const float* ins       = (const float*)d_in[1];
    const void*  resets    = d_in[2];
    const float* Wi        = (const float*)d_in[3];
    const float* bi        = (const float*)d_in[4];
    const float* Whrz      = (const float*)d_in[5];
    const float* Whn       = (const float*)d_in[6];
    const float* bhn       = (const float*)d_in[7];

    float* final_h = (float*)d_out;
    float* ys      = (float*)d_out + (size_t)B_ * H_;

    float* gi_ptr = nullptr;
    cudaGetSymbolAddress((void**)&gi_ptr, g_gi);

    cudaFuncSetAttribute(gru_scan_kernel,
                         cudaFuncAttributeMaxDynamicSharedMemorySize, SCAN_SMEM);

    prep_mask_kernel<<<1, 1024>>>(resets);

    gi_gemm_kernel<<<dim3(H3_ / 128, (T_ * B_) / 128), 256>>>(ins, Wi, bi, gi_ptr);

    // ncu alignment: 2 harness init launches + prep + gemm + noop => scan = #6
    noop_kernel<<<1, 32>>>();

    gru_scan_kernel<<<NBLK, NTHR, SCAN_SMEM>>>(rnn_state, Whrz, Whn, bhn,
                                               gi_ptr, ys);

    cudaMemcpyAsync(final_h, ys + (size_t)(T_ - 1) * B_ * H_,
                    (size_t)B_ * H_ * sizeof(float),
                    cudaMemcpyDeviceToDevice, 0);
}

// round 8
// speedup vs baseline: 5.1849x; 1.0551x over previous
#include <cuda_runtime.h>
#include <cuda_bf16.h>
#include <math.h>
#include <cstdint>

#define T_  512
#define B_  256
#define D_  512
#define H_  512
#define H2_ (2*H_)
#define H3_ (3*H_)

#define NBLK 128
#define NTHR 256

typedef unsigned long long ull;

// ===========================================================================
// Global scratch
// ===========================================================================
__device__ float g_gi[(size_t)T_ * B_ * H3_];          // gi = ins @ Wi + bi
__device__ float g_mask[T_ * B_];
__device__ __nv_bfloat16 g_ah[(size_t)T_ * B_ * D_];   // ins hi
__device__ __nv_bfloat16 g_al[(size_t)T_ * B_ * D_];   // ins lo
__device__ __nv_bfloat16 g_bh[(size_t)H3_ * D_];       // Wi^T hi  [n][k]
__device__ __nv_bfloat16 g_bl[(size_t)H3_ * D_];       // Wi^T lo
__device__ unsigned g_cnt8[8 * 32];
__device__ volatile unsigned g_gen8[8 * 32];

// ===========================================================================
// helpers
// ===========================================================================
__device__ __forceinline__ uint32_t smem_u32(const void* p) {
    uint32_t a;
    asm("{ .reg .u64 t; cvta.to.shared.u64 t, %1; cvt.u32.u64 %0, t; }"
        : "=r"(a) : "l"(p));
    return a;
}

#define LDSM4(R, A) \
    asm volatile("ldmatrix.sync.aligned.m8n8.x4.shared.b16 {%0,%1,%2,%3}, [%4];" \
        : "=r"((R)[0]), "=r"((R)[1]), "=r"((R)[2]), "=r"((R)[3]) : "r"(A))
#define LDSM2(R, A) \
    asm volatile("ldmatrix.sync.aligned.m8n8.x2.shared.b16 {%0,%1}, [%2];" \
        : "=r"((R)[0]), "=r"((R)[1]) : "r"(A))

__device__ __forceinline__ void mma4(float* c, const unsigned* a,
                                     unsigned b0, unsigned b1) {
    asm volatile(
        "mma.sync.aligned.m16n8k16.row.col.f32.bf16.bf16.f32 "
        "{%0,%1,%2,%3}, {%4,%5,%6,%7}, {%8,%9}, {%0,%1,%2,%3};"
        : "+f"(c[0]), "+f"(c[1]), "+f"(c[2]), "+f"(c[3])
        : "r"(a[0]), "r"(a[1]), "r"(a[2]), "r"(a[3]), "r"(b0), "r"(b1));
}

__device__ __forceinline__ void split_f4(float4 v, ull& hi, ull& lo) {
    __nv_bfloat16 h0 = __float2bfloat16(v.x);
    __nv_bfloat16 h1 = __float2bfloat16(v.y);
    __nv_bfloat16 h2 = __float2bfloat16(v.z);
    __nv_bfloat16 h3 = __float2bfloat16(v.w);
    __nv_bfloat16 l0 = __float2bfloat16(v.x - __bfloat162float(h0));
    __nv_bfloat16 l1 = __float2bfloat16(v.y - __bfloat162float(h1));
    __nv_bfloat16 l2 = __float2bfloat16(v.z - __bfloat162float(h2));
    __nv_bfloat16 l3 = __float2bfloat16(v.w - __bfloat162float(h3));
    unsigned short hu[4] = { *(unsigned short*)&h0, *(unsigned short*)&h1,
                             *(unsigned short*)&h2, *(unsigned short*)&h3 };
    unsigned short lu[4] = { *(unsigned short*)&l0, *(unsigned short*)&l1,
                             *(unsigned short*)&l2, *(unsigned short*)&l3 };
    hi = *(ull*)hu; lo = *(ull*)lu;
}

__device__ __forceinline__ void split_f1(float v, unsigned short& hi,
                                         unsigned short& lo) {
    __nv_bfloat16 h = __float2bfloat16(v);
    __nv_bfloat16 l = __float2bfloat16(v - __bfloat162float(h));
    hi = *(unsigned short*)&h;
    lo = *(unsigned short*)&l;
}

// ===========================================================================
// Reset-mask prep
// ===========================================================================
__global__ void prep_mask_kernel(const void* __restrict__ resets)
{
    const int N = T_ * B_;
    const unsigned char* b8 = (const unsigned char*)resets;
    int found = 0;
    for (int i = threadIdx.x; i < N; i += blockDim.x)
        if ((i & 3) && b8[i] == 1) found = 1;
    int is_byte = __syncthreads_or(found);
    if (is_byte) {
        for (int i = threadIdx.x; i < N; i += blockDim.x)
            g_mask[i] = b8[i] ? 0.0f : 1.0f;
    } else {
        const unsigned int* w32 = (const unsigned int*)resets;
        for (int i = threadIdx.x; i < N; i += blockDim.x)
            g_mask[i] = w32[i] ? 0.0f : 1.0f;
    }
}

// ===========================================================================
// Split conversions (one-shot)
// ===========================================================================
__global__ void conv_a_kernel(const float* __restrict__ ins)
{
    const size_t total = (size_t)T_ * B_ * D_ / 8;
    for (size_t i = (size_t)blockIdx.x * blockDim.x + threadIdx.x;
         i < total; i += (size_t)gridDim.x * blockDim.x) {
        size_t base = i * 8;
        float4 a = *(const float4*)(ins + base);
        float4 b = *(const float4*)(ins + base + 4);
        ull h0, l0, h1, l1;
        split_f4(a, h0, l0); split_f4(b, h1, l1);
        *(ull*)&g_ah[base] = h0; *(ull*)&g_ah[base + 4] = h1;
        *(ull*)&g_al[base] = l0; *(ull*)&g_al[base + 4] = l1;
    }
}

__global__ void conv_b_kernel(const float* __restrict__ Wi)
{
    const int total = H3_ * (D_ / 8);
    for (int i = blockIdx.x * blockDim.x + threadIdx.x;
         i < total; i += gridDim.x * blockDim.x) {
        int n = i % H3_;
        int k8 = (i / H3_) * 8;
        float4 a, b;
        a.x = Wi[(size_t)(k8+0)*H3_ + n]; a.y = Wi[(size_t)(k8+1)*H3_ + n];
        a.z = Wi[(size_t)(k8+2)*H3_ + n]; a.w = Wi[(size_t)(k8+3)*H3_ + n];
        b.x = Wi[(size_t)(k8+4)*H3_ + n]; b.y = Wi[(size_t)(k8+5)*H3_ + n];
        b.z = Wi[(size_t)(k8+6)*H3_ + n]; b.w = Wi[(size_t)(k8+7)*H3_ + n];
        ull h0, l0, h1, l1;
        split_f4(a, h0, l0); split_f4(b, h1, l1);
        size_t o = (size_t)n * D_ + k8;
        *(ull*)&g_bh[o] = h0; *(ull*)&g_bh[o + 4] = h1;
        *(ull*)&g_bl[o] = l0; *(ull*)&g_bl[o + 4] = l1;
    }
}

// ===========================================================================
// gi GEMM v2: precomputed bf16 blobs, ldmatrix frags, 128x128x32 tiles.
// ===========================================================================
#define SAK 40

__global__ __launch_bounds__(256)
void gi_gemm_kernel(const float* __restrict__ bias, float* __restrict__ C)
{
    __shared__ __nv_bfloat16 sAh[128 * SAK], sAl[128 * SAK];
    __shared__ __nv_bfloat16 sBh[128 * SAK], sBl[128 * SAK];

    const int tid = threadIdx.x;
    const int n0  = blockIdx.x * 128;
    const int m0  = blockIdx.y * 128;
    const int wid = tid >> 5, lane = tid & 31;
    const int wm = (wid & 1) * 64;
    const int wn = (wid >> 1) * 32;
    const int g  = lane >> 2;
    const int tg = lane & 3;

    // staging: row = tid>>1, k16 = (tid&1)*16
    const int sr = tid >> 1, sk = (tid & 1) * 16;
    const __nv_bfloat16* pAh = g_ah + (size_t)(m0 + sr) * D_ + sk;
    const __nv_bfloat16* pAl = g_al + (size_t)(m0 + sr) * D_ + sk;
    const __nv_bfloat16* pBh = g_bh + (size_t)(n0 + sr) * D_ + sk;
    const __nv_bfloat16* pBl = g_bl + (size_t)(n0 + sr) * D_ + sk;

    // ldmatrix lane offsets (bytes)
    const uint32_t aH = smem_u32(sAh) + (((wm + (lane & 15)) * SAK) +
                        ((lane & 16) ? 8 : 0)) * 2;
    const uint32_t aL = aH + (uint32_t)(sAl - sAh) * 2;
    const uint32_t bH = smem_u32(sBh) + (((wn + (lane & 7) +
                        ((lane & 16) ? 8 : 0)) * SAK) +
                        ((lane & 8) ? 8 : 0)) * 2;
    const uint32_t bL = bH + (uint32_t)(sBl - sBh) * 2;
    const int mstep = 16 * SAK * 2;
    const int nstep = 16 * SAK * 2;

    float acc[4][4][4];
    #pragma unroll
    for (int i = 0; i < 4; i++)
        #pragma unroll
        for (int j = 0; j < 4; j++)
            #pragma unroll
            for (int q = 0; q < 4; q++) acc[i][j][q] = 0.0f;

    uint4 rah0, rah1, ral0, ral1, rbh0, rbh1, rbl0, rbl1;
    rah0 = *(const uint4*)(pAh);     rah1 = *(const uint4*)(pAh + 8);
    ral0 = *(const uint4*)(pAl);     ral1 = *(const uint4*)(pAl + 8);
    rbh0 = *(const uint4*)(pBh);     rbh1 = *(const uint4*)(pBh + 8);
    rbl0 = *(const uint4*)(pBl);     rbl1 = *(const uint4*)(pBl + 8);

    for (int kc = 0; kc < D_ / 32; kc++) {
        __syncthreads();
        *(uint4*)&sAh[sr * SAK + sk] = rah0;  *(uint4*)&sAh[sr * SAK + sk + 8] = rah1;
        *(uint4*)&sAl[sr * SAK + sk] = ral0;  *(uint4*)&sAl[sr * SAK + sk + 8] = ral1;
        *(uint4*)&sBh[sr * SAK + sk] = rbh0;  *(uint4*)&sBh[sr * SAK + sk + 8] = rbh1;
        *(uint4*)&sBl[sr * SAK + sk] = rbl0;  *(uint4*)&sBl[sr * SAK + sk + 8] = rbl1;
        __syncthreads();

        if (kc + 1 < D_ / 32) {
            int k0 = (kc + 1) * 32;
            rah0 = *(const uint4*)(pAh + k0);  rah1 = *(const uint4*)(pAh + k0 + 8);
            ral0 = *(const uint4*)(pAl + k0);  ral1 = *(const uint4*)(pAl + k0 + 8);
            rbh0 = *(const uint4*)(pBh + k0);  rbh1 = *(const uint4*)(pBh + k0 + 8);
            rbl0 = *(const uint4*)(pBl + k0);  rbl1 = *(const uint4*)(pBl + k0 + 8);
        }

        #pragma unroll
        for (int ks = 0; ks < 2; ks++) {
            const int k2 = ks * 32;      // byte offset of 16-k slab
            unsigned bh01[4], bh23[4], bl01[4], bl23[4];
            LDSM4(bh01, bH + k2);
            LDSM4(bh23, bH + nstep + k2);
            LDSM4(bl01, bL + k2);
            LDSM4(bl23, bL + nstep + k2);
            #pragma unroll
            for (int mi = 0; mi < 4; mi++) {
                unsigned ah[4], al[4];
                LDSM4(ah, aH + mi * mstep + k2);
                LDSM4(al, aL + mi * mstep + k2);
                mma4(acc[mi][0], ah, bh01[0], bh01[1]);
                mma4(acc[mi][1], ah, bh01[2], bh01[3]);
                mma4(acc[mi][2], ah, bh23[0], bh23[1]);
                mma4(acc[mi][3], ah, bh23[2], bh23[3]);
                mma4(acc[mi][0], al, bh01[0], bh01[1]);
                mma4(acc[mi][1], al, bh01[2], bh01[3]);
                mma4(acc[mi][2], al, bh23[0], bh23[1]);
                mma4(acc[mi][3], al, bh23[2], bh23[3]);
                mma4(acc[mi][0], ah, bl01[0], bl01[1]);
                mma4(acc[mi][1], ah, bl01[2], bl01[3]);
                mma4(acc[mi][2], ah, bl23[0], bl23[1]);
                mma4(acc[mi][3], ah, bl23[2], bl23[3]);
            }
        }
    }

    #pragma unroll
    for (int ni = 0; ni < 4; ni++) {
        int col = n0 + wn + ni * 8 + tg * 2;
        float b0 = bias[col], b1 = bias[col + 1];
        #pragma unroll
        for (int mi = 0; mi < 4; mi++) {
            int row = m0 + wm + mi * 16 + g;
            float2 o0 = make_float2(acc[mi][ni][0] + b0, acc[mi][ni][1] + b1);
            float2 o1 = make_float2(acc[mi][ni][2] + b0, acc[mi][ni][3] + b1);
            *(float2*)(C + (size_t)row * H3_ + col) = o0;
            *(float2*)(C + (size_t)(row + 8) * H3_ + col) = o1;
        }
    }
}

// ===========================================================================
// Per-batch-group barrier (16 blocks / batch tile)
// ===========================================================================
__device__ __forceinline__ void group_sync(int grp)
{
    __syncthreads();
    if (threadIdx.x == 0) {
        unsigned g = g_gen8[grp * 32];
        __threadfence();
        if (atomicAdd(&g_cnt8[grp * 32], 1) == 15) {
            g_cnt8[grp * 32] = 0;
            __threadfence();
            g_gen8[grp * 32] = g + 1;
        } else {
            while (g_gen8[grp * 32] == g) { __nanosleep(32); }
        }
        __threadfence();
    }
    __syncthreads();
}

// ===========================================================================
// Persistent GRU scan v4: ldmatrix frags, 1 barrier/chunk, no mask staging.
// ===========================================================================
#define WKS  520
#define HKS  72
#define OFF_WLO  99840                 // 96*520*2
#define OFF_HS   199680                // 2*OFF_WLO
#define HSBUF    9216                  // per buffer: Ah 4608B + Al 4608B
#define GOUT_STR 100
#define SCAN_SMEM (OFF_HS + 2*HSBUF)   // 218112

__global__ __launch_bounds__(NTHR, 1)
void gru_scan_kernel(const float* __restrict__ rnn_state,
                     const float* __restrict__ Whrz,
                     const float* __restrict__ Whn,
                     const float* __restrict__ bhn,
                     const float* __restrict__ gi,
                     float* __restrict__ ys)
{
    extern __shared__ char smraw[];
    __nv_bfloat16* Whi = (__nv_bfloat16*)smraw;
    __nv_bfloat16* Wlo = (__nv_bfloat16*)(smraw + OFF_WLO);
    float* gout = (float*)(smraw + OFF_HS);

    const int tid = threadIdx.x;
    const int bid = blockIdx.x;
    const int hti = bid & 15, bti = bid >> 4;
    const int hb  = hti * 32;
    const int b0  = bti * 32;

    const int wid = tid >> 5, lane = tid & 31;
    const int wm  = (wid & 1) * 16;
    const int wn  = (wid >> 1) * 24;
    const int g   = lane >> 2;
    const int tg  = lane & 3;

    const int cm0 = tid >> 4;
    const int cm1 = 16 + cm0;
    const int ckq = (tid & 15) * 4;

    const int eb  = tid >> 3;
    const int eh4 = (tid & 7) * 4;

    const uint32_t smb = smem_u32(smraw);

    // ldmatrix lane offsets
    const uint32_t wH01 = smb + (((wn + (lane & 7) + ((lane & 16) ? 8 : 0)) * WKS)
                          + ((lane & 8) ? 8 : 0)) * 2;
    const uint32_t wH2  = smb + (((wn + 16 + (lane & 7)) * WKS)
                          + ((lane & 8) ? 8 : 0)) * 2;
    const uint32_t wL01 = wH01 + OFF_WLO;
    const uint32_t wL2  = wH2 + OFF_WLO;
    const uint32_t hOffA = (((wm + (lane & 15)) * HKS) + ((lane & 16) ? 8 : 0)) * 2;

    // ---- one-time: W slice -> bf16 hi/lo resident [96][WKS]
    for (int i = tid; i < 96 * 128; i += NTHR) {
        int n = i >> 7, kq = (i & 127) * 4;
        int gate = n >> 5, hcol = hb + (n & 31);
        const float* src;
        int stride;
        if (gate == 0)      { src = Whrz + hcol;      stride = H2_; }
        else if (gate == 1) { src = Whrz + H_ + hcol; stride = H2_; }
        else                { src = Whn + hcol;       stride = H_;  }
        unsigned short hv[4], lv[4];
        #pragma unroll
        for (int j = 0; j < 4; j++)
            split_f1(src[(size_t)(kq + j) * stride], hv[j], lv[j]);
        *(ull*)&Whi[n * WKS + kq] = *(ull*)hv;
        *(ull*)&Wlo[n * WKS + kq] = *(ull*)lv;
    }

    const float4 bh4 = *(const float4*)(bhn + hb + eh4);

    for (int t = 0; t < T_; t++) {
        const float* hin = (t == 0) ? rnn_state : (ys + (size_t)(t - 1) * B_ * H_);

        const float m0 = __ldg(&g_mask[t * B_ + b0 + cm0]);
        const float m1 = __ldg(&g_mask[t * B_ + b0 + cm1]);
        const float me = __ldg(&g_mask[t * B_ + b0 + eb]);

        // epilogue prefetch
        const float* gib = gi + ((size_t)t * B_ + b0 + eb) * H3_ + hb + eh4;
        float4 ir4 = __ldcg((const float4*)(gib));
        float4 iz4 = __ldcg((const float4*)(gib + H_));
        float4 in4 = __ldcg((const float4*)(gib + 2 * H_));
        float4 ho4 = __ldcg((const float4*)(hin + (size_t)(b0 + eb) * H_ + hb + eh4));

        const float* hr0 = hin + (size_t)(b0 + cm0) * H_ + ckq;
        const float* hr1 = hin + (size_t)(b0 + cm1) * H_ + ckq;
        float4 v0 = __ldcg((const float4*)hr0);
        float4 v1 = __ldcg((const float4*)hr1);

        float acc[3][4];
        #pragma unroll
        for (int ni = 0; ni < 3; ni++)
            #pragma unroll
            for (int q = 0; q < 4; q++) acc[ni][q] = 0.0f;

        for (int c = 0; c < 8; c++) {
            char* hbuf = smraw + OFF_HS + (c & 1) * HSBUF;
            __nv_bfloat16* hsAh = (__nv_bfloat16*)hbuf;
            __nv_bfloat16* hsAl = (__nv_bfloat16*)(hbuf + 4608);
            {
                ull hi, lo;
                split_f4(make_float4(v0.x*m0, v0.y*m0, v0.z*m0, v0.w*m0), hi, lo);
                *(ull*)&hsAh[cm0 * HKS + ckq] = hi;
                *(ull*)&hsAl[cm0 * HKS + ckq] = lo;
                split_f4(make_float4(v1.x*m1, v1.y*m1, v1.z*m1, v1.w*m1), hi, lo);
                *(ull*)&hsAh[cm1 * HKS + ckq] = hi;
                *(ull*)&hsAl[cm1 * HKS + ckq] = lo;
            }
            __syncthreads();

            if (c < 7) {
                int off = (c + 1) * 64;
                v0 = __ldcg((const float4*)(hr0 + off));
                v1 = __ldcg((const float4*)(hr1 + off));
            }

            const uint32_t hA = smb + OFF_HS + (c & 1) * HSBUF + hOffA;
            const uint32_t hAlo = hA + 4608;

            #pragma unroll
            for (int ks = 0; ks < 4; ks++) {
                const int kw2 = (c * 64 + ks * 16) * 2;
                const int kl2 = ks * 32;
                unsigned wh01[4], wh2[2], wl01[4], wl2[2];
                LDSM4(wh01, wH01 + kw2);
                LDSM2(wh2,  wH2 + kw2);
                LDSM4(wl01, wL01 + kw2);
                LDSM2(wl2,  wL2 + kw2);
                unsigned ah[4], al[4];
                LDSM4(ah, hA + kl2);
                LDSM4(al, hAlo + kl2);
                mma4(acc[0], ah, wh01[0], wh01[1]);
                mma4(acc[1], ah, wh01[2], wh01[3]);
                mma4(acc[2], ah, wh2[0], wh2[1]);
                mma4(acc[0], al, wh01[0], wh01[1]);
                mma4(acc[1], al, wh01[2], wh01[3]);
                mma4(acc[2], al, wh2[0], wh2[1]);
                mma4(acc[0], ah, wl01[0], wl01[1]);
                mma4(acc[1], ah, wl01[2], wl01[3]);
                mma4(acc[2], ah, wl2[0], wl2[1]);
            }
        }

        // ---- epilogue
        __syncthreads();
        #pragma unroll
        for (int ni = 0; ni < 3; ni++) {
            int col = wn + ni * 8 + tg * 2;
            *(float2*)&gout[(wm + g) * GOUT_STR + col] =
                make_float2(acc[ni][0], acc[ni][1]);
            *(float2*)&gout[(wm + g + 8) * GOUT_STR + col] =
                make_float2(acc[ni][2], acc[ni][3]);
        }
        __syncthreads();

        {
            float4 cr = *(const float4*)&gout[eb * GOUT_STR + eh4];
            float4 cz = *(const float4*)&gout[eb * GOUT_STR + 32 + eh4];
            float4 cn = *(const float4*)&gout[eb * GOUT_STR + 64 + eh4];

            float hm[4] = { ho4.x * me, ho4.y * me, ho4.z * me, ho4.w * me };
            float irv[4] = { ir4.x, ir4.y, ir4.z, ir4.w };
            float izv[4] = { iz4.x, iz4.y, iz4.z, iz4.w };
            float inv[4] = { in4.x, in4.y, in4.z, in4.w };
            float crv[4] = { cr.x, cr.y, cr.z, cr.w };
            float czv[4] = { cz.x, cz.y, cz.z, cz.w };
            float cnv[4] = { cn.x, cn.y, cn.z, cn.w };
            float bhv[4] = { bh4.x, bh4.y, bh4.z, bh4.w };

            float out[4];
            #pragma unroll
            for (int j = 0; j < 4; j++) {
                float r = 1.0f / (1.0f + __expf(-(irv[j] + crv[j])));
                float z = 1.0f / (1.0f + __expf(-(izv[j] + czv[j])));
                float e = __expf(2.0f * (inv[j] + r * (cnv[j] + bhv[j])));
                float n = __fdividef(e - 1.0f, e + 1.0f);
                out[j] = (1.0f - z) * n + z * hm[j];
            }
            *(float4*)(ys + ((size_t)t * B_ + b0 + eb) * H_ + hb + eh4) =
                make_float4(out[0], out[1], out[2], out[3]);
        }

        group_sync(bti);
    }
}

// ===========================================================================
extern "C" void kernel_launch(void* const* d_in, const int* in_sizes, int n_in,
                              void* d_out, int out_size)
{
    const float* rnn_state = (const float*)d_in[0];
    const float* ins       = (const float*)d_in[1];
    const void*  resets    = d_in[2];
    const float* Wi        = (const float*)d_in[3];
    const float* bi        = (const float*)d_in[4];
    const float* Whrz      = (const float*)d_in[5];
    const float* Whn       = (const float*)d_in[6];
    const float* bhn       = (const float*)d_in[7];

    float* final_h = (float*)d_out;
    float* ys      = (float*)d_out + (size_t)B_ * H_;

    float* gi_ptr = nullptr;
    cudaGetSymbolAddress((void**)&gi_ptr, g_gi);

    cudaFuncSetAttribute(gru_scan_kernel,
                         cudaFuncAttributeMaxDynamicSharedMemorySize, SCAN_SMEM);

    prep_mask_kernel<<<1, 1024>>>(resets);
    conv_a_kernel<<<2048, 256>>>(ins);
    conv_b_kernel<<<96, 256>>>(Wi);

    // gemm is launch #6 for the ncu -s 5 -c 1 window (2 harness init launches)
    gi_gemm_kernel<<<dim3(H3_ / 128, (T_ * B_) / 128), 256>>>(bi, gi_ptr);

    gru_scan_kernel<<<NBLK, NTHR, SCAN_SMEM>>>(rnn_state, Whrz, Whn, bhn,
                                               gi_ptr, ys);

    cudaMemcpyAsync(final_h, ys + (size_t)(T_ - 1) * B_ * H_,
                    (size_t)B_ * H_ * sizeof(float),
                    cudaMemcpyDeviceToDevice, 0);
}